// round 14
// baseline (speedup 1.0000x reference)
#include <cuda_runtime.h>
#include <cuda_bf16.h>
#include <cuda_fp16.h>
#include <math.h>
#include <cstdint>

#define NB 4
#define C 128
#define CC 64
#define H0 256
#define HD 64
#define EPS6 1e-6f
#define BN_INV 0.9999950000374997f
#define E1F 2.7182818284590452f

// ---------- helpers ----------
__device__ __forceinline__ uint32_t s2u(const void* p){
    uint32_t a; asm("{ .reg .u64 t; cvta.to.shared.u64 t, %1; cvt.u32.u64 %0, t; }" : "=r"(a) : "l"(p)); return a;
}
__device__ __forceinline__ void ldsm4(uint32_t* r, uint32_t a){
    asm volatile("ldmatrix.sync.aligned.m8n8.x4.shared.b16 {%0,%1,%2,%3}, [%4];"
        : "=r"(r[0]),"=r"(r[1]),"=r"(r[2]),"=r"(r[3]) : "r"(a));
}
__device__ __forceinline__ void ldsm4t(uint32_t* r, uint32_t a){
    asm volatile("ldmatrix.sync.aligned.m8n8.x4.trans.shared.b16 {%0,%1,%2,%3}, [%4];"
        : "=r"(r[0]),"=r"(r[1]),"=r"(r[2]),"=r"(r[3]) : "r"(a));
}
__device__ __forceinline__ void mma16816(float* d, const uint32_t* a, uint32_t b0, uint32_t b1){
    asm volatile("mma.sync.aligned.m16n8k16.row.col.f32.bf16.bf16.f32 "
        "{%0,%1,%2,%3}, {%4,%5,%6,%7}, {%8,%9}, {%0,%1,%2,%3};"
        : "+f"(d[0]),"+f"(d[1]),"+f"(d[2]),"+f"(d[3])
        : "r"(a[0]),"r"(a[1]),"r"(a[2]),"r"(a[3]), "r"(b0),"r"(b1));
}
// exp(x) for x in [0, 1.2]: half-and-square Taylor deg 6, rel err < 6e-6. Pure FMA.
__device__ __forceinline__ float expp(float x){
    float h = 0.5f*x;
    float p = __fmaf_rn(h, 0.0013888889f, 0.0083333333f);
    p = __fmaf_rn(h, p, 0.0416666667f);
    p = __fmaf_rn(h, p, 0.1666666667f);
    p = __fmaf_rn(h, p, 0.5f);
    p = __fmaf_rn(h, p, 1.0f);
    p = __fmaf_rn(h, p, 1.0f);
    return p*p;
}
__device__ __forceinline__ float sum8bf(uint4 v){
    const __nv_bfloat162* h = (const __nv_bfloat162*)&v;
    float s = 0.f;
    #pragma unroll
    for (int i=0;i<4;i++){ float2 f = __bfloat1622float2(h[i]); s += f.x + f.y; }
    return s;
}

// ---------- scratch ----------
__device__ __align__(16) __nv_bfloat16 g_wcat[192*128];
__device__ __align__(16) __nv_bfloat16 g_zw_h[128*64];
__device__ __align__(16) __nv_bfloat16 g_owcat[3*64*128];
__device__ __align__(16) __nv_bfloat16 g_thin [NB*CC*HD*HD];
__device__ __align__(16) __nv_bfloat16 g_g0   [NB*CC*1024];
__device__ __align__(16) __nv_bfloat16 g_phi0 [NB*CC*1024];
__device__ float g_poolT[3*NB*85*64];
__device__ float g_ppc  [3][NB*85*16];
__device__ __align__(16) __nv_bfloat16 g_th_h [NB*4096*64];
__device__ __align__(16) __nv_bfloat16 g_phi_h[NB*1024*64];
__device__ __align__(16) __nv_bfloat16 g_gv_h [NB*1024*64];
__device__ uint32_t g_lg[NB*4096*512];
__device__ float g_z[NB*C*4096];

// ---------- K0: weight prep ----------
__global__ void k_prep(const float* __restrict__ tw, const float* __restrict__ gw,
                       const float* __restrict__ pw, const float* __restrict__ zw,
                       const float* __restrict__ ow0, const float* __restrict__ ow1,
                       const float* __restrict__ ow2){
    int i = blockIdx.x*256 + threadIdx.x;
    if (i < 3*8192){
        int m = i >> 13;
        const float* src = (m==0) ? tw : (m==1) ? gw : pw;
        g_wcat[i] = __float2bfloat16(src[i & 8191]);
    } else if (i < 4*8192){
        g_zw_h[i - 3*8192] = __float2bfloat16(zw[i - 3*8192]);
    } else if (i < 7*8192){
        int m = (i - 4*8192) >> 13;
        const float* src = (m==0) ? ow0 : (m==1) ? ow1 : ow2;
        g_owcat[i - 4*8192] = __float2bfloat16(src[(i - 4*8192) & 8191]);
    }
}

// ---------- K1: fused down-conv + theta/g/phi HMMA convs + maxpool ----------
__global__ void __launch_bounds__(384) k_convs_hmma(const float* __restrict__ x,
                        const float* __restrict__ dw,
                        const float* __restrict__ tb_,
                        const float* __restrict__ gb_, const float* __restrict__ pb_){
    __shared__ __nv_bfloat16 sX[2][128][72];
    __shared__ float sdw[128][16];
    int tid = threadIdx.x, w = tid>>5, lane = tid&31;
    int n = blockIdx.x >> 5;
    int tb = blockIdx.x & 31;
    int px0 = tb * 128;

    // stage depthwise weights
    for (int i=tid; i<2048; i+=384) sdw[i>>4][i&15] = dw[i];

    int r = lane>>2, cq = (lane&3)*2;
    uint32_t aW[8][4];
    {
        const __nv_bfloat16* w0 = g_wcat + (w*16 + r)*128;
        const __nv_bfloat16* w8 = w0 + 8*128;
        #pragma unroll
        for (int kb=0;kb<8;kb++){
            int c0 = kb*16 + cq;
            aW[kb][0] = *(const uint32_t*)&w0[c0];
            aW[kb][1] = *(const uint32_t*)&w8[c0];
            aW[kb][2] = *(const uint32_t*)&w0[c0+8];
            aW[kb][3] = *(const uint32_t*)&w8[c0+8];
        }
    }
    __syncthreads();
    // fused downsample: compute x_down tile directly from x
    for (int idx = tid; idx < 16384; idx += 384){
        int c = idx >> 7, i = idx & 127;
        int row = 2*tb + (i>>6), col = i&63;
        const float* xb = x + (((size_t)(n*C + c))<<16) + (row*4)*256 + col*4;
        const float* wv = &sdw[c][0];
        float s = 0.f;
        #pragma unroll
        for (int a=0;a<4;a++){
            float4 v = *(const float4*)(xb + a*256);
            s += v.x*wv[a*4+0] + v.y*wv[a*4+1] + v.z*wv[a*4+2] + v.w*wv[a*4+3];
        }
        sX[i>>6][c][i&63] = __float2bfloat16(s);
    }
    __syncthreads();

    int grow = (lane&7) + ((lane&8)?8:0);
    int gcol = (lane&16)?8:0;
    int brn = w >> 2, o0 = (w&3)*16;
    const float* bias = (brn==0) ? tb_ : (brn==1) ? gb_ : pb_;
    float ba = bias[o0 + r], bb = bias[o0 + r + 8];
    int colb = (lane&3)*2;

    float hm0[2][8], hm8[2][8];
    __nv_bfloat16* row0 = g_thin + ((size_t)n*CC + o0 + r)*4096 + px0;
    __nv_bfloat16* row8 = row0 + 8*4096;

    #pragma unroll
    for (int t=0;t<2;t++){
        float acc[8][4];
        #pragma unroll
        for (int i=0;i<8;i++){ acc[i][0]=0.f;acc[i][1]=0.f;acc[i][2]=0.f;acc[i][3]=0.f; }
        #pragma unroll
        for (int kb=0;kb<8;kb++){
            int kr = kb*16 + grow;
            #pragma unroll
            for (int np=0;np<4;np++){
                uint32_t bg[4];
                ldsm4t(bg, s2u(&sX[t][kr][np*16 + gcol]));
                mma16816(acc[2*np], aW[kb], bg[0], bg[1]);
                mma16816(acc[2*np+1], aW[kb], bg[2], bg[3]);
            }
        }
        if (brn == 0){
            #pragma unroll
            for (int nf=0;nf<8;nf++){
                int px = t*64 + nf*8 + colb;
                __nv_bfloat162 v0 = __floats2bfloat162_rn(acc[nf][0]+ba, acc[nf][1]+ba);
                __nv_bfloat162 v8 = __floats2bfloat162_rn(acc[nf][2]+bb, acc[nf][3]+bb);
                *(uint32_t*)&row0[px] = *(uint32_t*)&v0;
                *(uint32_t*)&row8[px] = *(uint32_t*)&v8;
            }
        } else {
            #pragma unroll
            for (int nf=0;nf<8;nf++){
                hm0[t][nf] = fmaxf(acc[nf][0], acc[nf][1]);
                hm8[t][nf] = fmaxf(acc[nf][2], acc[nf][3]);
            }
        }
    }
    if (brn != 0){
        __nv_bfloat16* dst = ((brn==1) ? g_g0 : g_phi0) + ((size_t)n*CC + o0 + r)*1024 + tb*32;
        int vx = lane&3;
        #pragma unroll
        for (int nf=0;nf<8;nf++){
            dst[nf*4 + vx]          = __float2bfloat16(fmaxf(hm0[0][nf], hm0[1][nf]) + ba);
            dst[8*1024 + nf*4 + vx] = __float2bfloat16(fmaxf(hm8[0][nf], hm8[1][nf]) + bb);
        }
    }
}

// ---------- K2: pyramid pools (bf16 in, fp32 out transposed) ----------
__global__ void __launch_bounds__(256) k_pool_all(){
    __shared__ float sp[4][64];
    __shared__ float s8[64], s4[16], s2[4];
    int bid = blockIdx.x;                 // 3*NB*64
    int br = bid >> 8; int nc = bid & 255;
    int n = nc >> 6, c = nc & 63;
    int bn = br*NB + n;
    int H = (br==1) ? 64 : 32;
    const __nv_bfloat16* in = (br==0) ? g_g0 : (br==1) ? g_thin : g_phi0;
    const __nv_bfloat16* p = in + (size_t)nc*H*H;
    int t = threadIdx.x & 63, q = threadIdx.x >> 6;
    int k0 = H >> 3;
    int cy = t>>3, cx = t&7;
    const __nv_bfloat16* cell = p + (cy*k0)*H + cx*k0;
    float s = 0.f;
    if (k0 == 8){
        #pragma unroll
        for (int a=0;a<2;a++){
            const uint4* rp = (const uint4*)(cell + (q*2+a)*H);
            s += sum8bf(rp[0]);
        }
    } else {
        const __nv_bfloat162* hp = (const __nv_bfloat162*)(cell + q*H);
        float2 f0 = __bfloat1622float2(hp[0]);
        float2 f1 = __bfloat1622float2(hp[1]);
        s = f0.x+f0.y+f1.x+f1.y;
    }
    sp[q][t] = s;
    __syncthreads();
    float* ob = g_poolT + (size_t)bn*85*64 + c;
    if (threadIdx.x < 64){
        float tot = sp[0][threadIdx.x]+sp[1][threadIdx.x]+sp[2][threadIdx.x]+sp[3][threadIdx.x];
        s8[threadIdx.x] = tot;
        ob[threadIdx.x*64] = tot / (float)(k0*k0);
    }
    __syncthreads();
    if (threadIdx.x < 16){
        int tt = threadIdx.x;
        int yy=tt>>2, xx=tt&3;
        float v = s8[(2*yy)*8+2*xx] + s8[(2*yy)*8+2*xx+1] + s8[(2*yy+1)*8+2*xx] + s8[(2*yy+1)*8+2*xx+1];
        s4[tt]=v; ob[(64+tt)*64] = v / (float)(4*k0*k0);
    }
    __syncthreads();
    if (threadIdx.x < 4){
        int tt = threadIdx.x;
        int yy=tt>>1, xx=tt&1;
        float v = s4[(2*yy)*4+2*xx] + s4[(2*yy)*4+2*xx+1] + s4[(2*yy+1)*4+2*xx] + s4[(2*yy+1)*4+2*xx+1];
        s2[tt]=v; ob[(80+tt)*64] = v / (float)(16*k0*k0);
    }
    __syncthreads();
    if (threadIdx.x == 0) ob[84*64] = (s2[0]+s2[1]+s2[2]+s2[3]) / (float)(64*k0*k0);
}

// ---------- K3: level convs ----------
__global__ void k_levelconv_all(const float* __restrict__ pw0, const float* __restrict__ g0, const float* __restrict__ b0,
                                const float* __restrict__ pw1, const float* __restrict__ g1, const float* __restrict__ b1,
                                const float* __restrict__ pw2, const float* __restrict__ g2, const float* __restrict__ b2){
    int idx = blockIdx.x*blockDim.x + threadIdx.x;
    if (idx >= 3*NB*85*16) return;
    int o = idx & 15;
    int s = (idx>>4) % 85;
    int bn = idx / (85*16);
    int br = bn >> 2, nn = bn & 3;
    const float* pw = (br==0)?pw0:(br==1)?pw1:pw2;
    const float* gamma = (br==0)?g0:(br==1)?g1:g2;
    const float* beta = (br==0)?b0:(br==1)?b1:b2;
    int lvl = (s<64) ? 0 : (s<80 ? 1 : (s<84 ? 2 : 3));
    const float4* w4 = (const float4*)(pw + (lvl*16+o)*64);
    const float4* p4 = (const float4*)(g_poolT + (size_t)bn*85*64 + s*64);
    float acc = 0.f;
    #pragma unroll
    for (int i=0;i<16;i++){
        float4 a = __ldg(&w4[i]);
        float4 b = p4[i];
        acc += a.x*b.x + a.y*b.y + a.z*b.z + a.w*b.w;
    }
    acc = acc*BN_INV*__ldg(&gamma[lvl*16+o]) + __ldg(&beta[lvl*16+o]);
    g_ppc[br][(nn*85+s)*16+o] = fmaxf(acc, 0.f);
}

// ---------- K4: pyramid final convs via HMMA ----------
__global__ void __launch_bounds__(256) k_ppfinal_all(
        const float* __restrict__ ob0, const float* __restrict__ ob1, const float* __restrict__ ob2){
    __shared__ __nv_bfloat16 sB[128][72];
    __shared__ __nv_bfloat16 sO[64][72];
    __shared__ float spp[85*16];
    int bid = blockIdx.x;
    int br, n, t0;
    if (bid < 256){ br = 1; n = bid>>6; t0 = (bid&63)<<6; }
    else {
        int r = bid - 256;
        br = (r < 64) ? 0 : 2;
        int r2 = r & 63;
        n = r2 >> 4; t0 = (r2 & 15) << 6;
    }
    const float* ob = (br==0)?ob0:(br==1)?ob1:ob2;
    int H = (br==1) ? 64 : 32;
    int P = H*H;
    const __nv_bfloat16* X = (br==0) ? g_g0 : (br==1) ? g_thin : g_phi0;
    const __nv_bfloat16* xin = X + (size_t)n*CC*P;
    int tid = threadIdx.x, w = tid>>5, lane = tid&31;
    for (int i=tid; i<512; i+=256){
        int c = i>>3, p8 = (i&7)*8;
        *(uint4*)&sB[c][p8] = *(const uint4*)&xin[c*P + t0 + p8];
    }
    for (int i=tid; i<1360; i+=256) spp[i] = g_ppc[br][n*1360 + i];
    __syncthreads();
    float invH = 1.0f / (float)H;
    for (int e = tid; e < 4096; e += 256){
        int u = e>>6, p = e&63;
        int lvl = u>>4, j = u&15;
        int pix = t0 + p; int y = pix / H, x = pix % H;
        int ps = 8 >> lvl;
        int off = (lvl==0) ? 0 : (lvl==1 ? 64 : (lvl==2 ? 80 : 84));
        float sy = fminf(fmaxf((y+0.5f)*ps*invH - 0.5f, 0.f), (float)(ps-1));
        float sx = fminf(fmaxf((x+0.5f)*ps*invH - 0.5f, 0.f), (float)(ps-1));
        int yl=(int)sy; int yh=min(yl+1, ps-1); float fy=sy-yl;
        int xl=(int)sx; int xh=min(xl+1, ps-1); float fx=sx-xl;
        const float* b00 = spp + (off + yl*ps + xl)*16;
        const float* b01 = spp + (off + yl*ps + xh)*16;
        const float* b10 = spp + (off + yh*ps + xl)*16;
        const float* b11 = spp + (off + yh*ps + xh)*16;
        float v = (b00[j]*(1.f-fx)+b01[j]*fx)*(1.f-fy) + (b10[j]*(1.f-fx)+b11[j]*fx)*fy;
        sB[64+u][p] = __float2bfloat16(v);
    }
    __syncthreads();
    int mt = w & 3, ph = w >> 2;
    int ra = lane>>2, colb = (lane&3)*2, cq = (lane&3)*2;
    uint32_t aW[8][4];
    {
        const __nv_bfloat16* w0 = g_owcat + br*8192 + (mt*16 + ra)*128;
        const __nv_bfloat16* w8 = w0 + 8*128;
        #pragma unroll
        for (int kb=0;kb<8;kb++){
            int c0 = kb*16 + cq;
            aW[kb][0] = *(const uint32_t*)&w0[c0];
            aW[kb][1] = *(const uint32_t*)&w8[c0];
            aW[kb][2] = *(const uint32_t*)&w0[c0+8];
            aW[kb][3] = *(const uint32_t*)&w8[c0+8];
        }
    }
    int grow = (lane&7) + ((lane&8)?8:0);
    int gcol = (lane&16)?8:0;
    float acc[4][4];
    #pragma unroll
    for (int i=0;i<4;i++){ acc[i][0]=0.f;acc[i][1]=0.f;acc[i][2]=0.f;acc[i][3]=0.f; }
    #pragma unroll
    for (int kb=0;kb<8;kb++){
        int kr = kb*16 + grow;
        #pragma unroll
        for (int np=0;np<2;np++){
            uint32_t bg[4];
            ldsm4t(bg, s2u(&sB[kr][ph*32 + np*16 + gcol]));
            mma16816(acc[2*np], aW[kb], bg[0], bg[1]);
            mma16816(acc[2*np+1], aW[kb], bg[2], bg[3]);
        }
    }
    float ba = ob[mt*16 + ra], bb = ob[mt*16 + ra + 8];
    #pragma unroll
    for (int nf=0;nf<4;nf++){
        int px = ph*32 + (nf>>1)*16 + (nf&1)*8 + colb;
        sO[px][mt*16+ra]     = __float2bfloat16(acc[nf][0]+ba);
        sO[px+1][mt*16+ra]   = __float2bfloat16(acc[nf][1]+ba);
        sO[px][mt*16+ra+8]   = __float2bfloat16(acc[nf][2]+bb);
        sO[px+1][mt*16+ra+8] = __float2bfloat16(acc[nf][3]+bb);
    }
    __syncthreads();
    __nv_bfloat16* dst = (br==1) ? (g_th_h + ((size_t)n*4096 + t0)*64)
                      : (br==0) ? (g_gv_h + ((size_t)n*1024 + t0)*64)
                                : (g_phi_h + ((size_t)n*1024 + t0)*64);
    for (int i=tid; i<512; i+=256){
        int px = i>>3, o8 = (i&7)*8;
        *(uint4*)&dst[px*64 + o8] = *(const uint4*)&sO[px][o8];
    }
}

// ---------- bilinear on 256x256 ----------
__device__ __forceinline__ float bil256(const float* p, float sy, float sx){
    int yl=(int)sy; int yh=min(yl+1,255); float fy=sy-yl;
    int xl=(int)sx; int xh=min(xl+1,255); float fx=sx-xl;
    return (p[yl*256+xl]*(1.f-fx)+p[yl*256+xh]*fx)*(1.f-fy)
         + (p[yh*256+xl]*(1.f-fx)+p[yh*256+xh]*fx)*fy;
}

// ---------- K5: HMMA attention + fused z-conv epilogue ----------
__global__ void __launch_bounds__(512,1) k_attn_hmma(const float* __restrict__ depth,
                                                     const float* __restrict__ zb){
    __shared__ __align__(16) char RAW[36864];
    __shared__ float2 d2s[1024];
    __shared__ float d1s[128];
    __shared__ float ss3[2][128];
    __nv_bfloat16* sA = (__nv_bfloat16*)RAW;
    __nv_bfloat16* sB = (__nv_bfloat16*)(RAW + 18432);
    float* STF = (float*)RAW;
    int tid = threadIdx.x, w = tid>>5, lane = tid&31;
    int qt = w & 7, nh = w >> 3;
    int n = blockIdx.x>>5, q0 = (blockIdx.x&31)*128;

    const float* dm = depth + (size_t)n*65536;
    for (int i=tid;i<1024;i+=512){
        int yy=i>>5, xx=i&31;
        float d2 = bil256(dm, (float)(yy*255)/31.f, (float)(xx*255)/31.f);
        d2s[i] = make_float2(d2, __fdividef(1.f, d2+EPS6));
    }
    if (tid < 128){
        int q = q0 + tid;
        d1s[tid] = bil256(dm, (float)((q>>6)*255)/63.f, (float)((q&63)*255)/63.f);
    }
    const uint4* qg = (const uint4*)(g_th_h + ((size_t)(n*4096+q0))*64);
    for (int i=tid;i<1024;i+=512)
        *(uint4*)&sA[(i>>3)*72 + (i&7)*8] = qg[i];
    __syncthreads();
    uint32_t sAu = s2u(sA), sBu = s2u(sB);
    uint32_t aQ[4][4];
    {
        int arow = qt*16 + (lane&15);
        int acol = (lane>>4)<<3;
        #pragma unroll
        for (int kb=0;kb<4;kb++)
            ldsm4(aQ[kb], sAu + (uint32_t)((arow*72 + kb*16 + acol)*2));
    }
    int ra = lane>>2, colb = (lane&3)*2;
    int r0_ = qt*16 + ra, r1_ = r0_ + 8;
    float d1a = d1s[r0_], d1b = d1s[r1_];
    float ir1a = __fdividef(1.f,d1a+EPS6), ir1b = __fdividef(1.f,d1b+EPS6);
    __syncthreads();

    int brow = (lane&7) + ((lane&16)?8:0);
    int bcol = (lane&8)?8:0;
    int grow = (lane&7) + ((lane&8)?8:0);
    int gcol = (lane&16)?8:0;
    const uint4* phg = (const uint4*)(g_phi_h + (size_t)n*65536);
    const uint4* gg  = (const uint4*)(g_gv_h + (size_t)n*65536);
    uint32_t* lg = g_lg + ((size_t)(n*4096 + q0))*512;
    int lrowa = r0_*512, lrowb = r1_*512;

    float s1a=0.f, s2a=0.f, s1b=0.f, s2b=0.f;

    for (int i=tid;i<1024;i+=512)
        *(uint4*)&sA[(i>>3)*72+(i&7)*8] = phg[i];
    __syncthreads();

    // ===== pass 1: all-MUFU exps; w=exp(l+r) stored fp16 =====
    for (int t=0;t<8;t++){
        uint32_t curu = (t&1) ? sBu : sAu;
        __nv_bfloat16* nxt = (t&1) ? sA : sB;
        uint4 pre0, pre1;
        if (t<7){ pre0 = phg[(t+1)*1024 + tid]; pre1 = phg[(t+1)*1024 + tid + 512]; }
        float L[8][4];
        #pragma unroll
        for (int nt=0;nt<8;nt++){ L[nt][0]=0.f;L[nt][1]=0.f;L[nt][2]=0.f;L[nt][3]=0.f; }
        #pragma unroll
        for (int kb=0;kb<4;kb++){
            #pragma unroll
            for (int ng=0;ng<4;ng++){
                uint32_t bq[4];
                int br_ = nh*64 + ng*16 + brow;
                ldsm4(bq, curu + (uint32_t)((br_*72 + kb*16 + bcol)*2));
                mma16816(L[2*ng], aQ[kb], bq[0], bq[1]);
                mma16816(L[2*ng+1], aQ[kb], bq[2], bq[3]);
            }
        }
        if (t<7){
            int i0 = tid;       *(uint4*)&nxt[(i0>>3)*72+(i0&7)*8] = pre0;
            i0 = tid + 512;     *(uint4*)&nxt[(i0>>3)*72+(i0&7)*8] = pre1;
        }
        int cwb = t*64 + nh*32 + (lane&3);
        #pragma unroll
        for (int nt=0;nt<8;nt++){
            int v = t*128 + nh*64 + nt*8 + colb;
            float2 dp = d2s[v], dq = d2s[v+1];
            float r0 = fminf(d1a*dp.y, dp.x*ir1a);
            float r1 = fminf(d1a*dq.y, dq.x*ir1a);
            float r2 = fminf(d1b*dp.y, dp.x*ir1b);
            float r3 = fminf(d1b*dq.y, dq.x*ir1b);
            s2a += __expf(r0-1.f) + __expf(r1-1.f);
            s2b += __expf(r2-1.f) + __expf(r3-1.f);
            s1a += __expf(L[nt][0]) + __expf(L[nt][1]);
            s1b += __expf(L[nt][2]) + __expf(L[nt][3]);
            __half2 ha = __floats2half2_rn(__expf(L[nt][0]+r0), __expf(L[nt][1]+r1));
            __half2 hb = __floats2half2_rn(__expf(L[nt][2]+r2), __expf(L[nt][3]+r3));
            lg[lrowa + cwb + nt*4] = *(uint32_t*)&ha;
            lg[lrowb + cwb + nt*4] = *(uint32_t*)&hb;
        }
        __syncthreads();
    }

    #pragma unroll
    for (int o=1;o<=2;o<<=1){
        s1a += __shfl_xor_sync(~0u,s1a,o);
        s1b += __shfl_xor_sync(~0u,s1b,o);
        s2a += __shfl_xor_sync(~0u,s2a,o);
        s2b += __shfl_xor_sync(~0u,s2b,o);
    }
    if ((lane&3)==0){
        STF[      nh*128 + r0_] = s1a;  STF[      nh*128 + r1_] = s1b;
        STF[256 + nh*128 + r0_] = s2a;  STF[256 + nh*128 + r1_] = s2b;
    }
    __syncthreads();
    float S1a = STF[r0_] + STF[128+r0_];
    float S2a = (STF[256+r0_] + STF[256+128+r0_]) * E1F;
    float S1b = STF[r1_] + STF[128+r1_];
    float S2b = (STF[256+r1_] + STF[256+128+r1_]) * E1F;
    float c1a = __fdividef(1.f, S1a*S2a);
    float c1b = __fdividef(1.f, S1b*S2b);
    __syncthreads();

    // ===== pass 2 =====
    float Y[8][4];
    #pragma unroll
    for (int i=0;i<8;i++){ Y[i][0]=0.f;Y[i][1]=0.f;Y[i][2]=0.f;Y[i][3]=0.f; }
    float s3a=0.f, s3b=0.f;
    for (int i=tid;i<1024;i+=512)
        *(uint4*)&sA[(i>>3)*72+(i&7)*8] = gg[i];
    __syncthreads();
    for (int t=0;t<8;t++){
        uint32_t curu = (t&1) ? sBu : sAu;
        __nv_bfloat16* nxt = (t&1) ? sA : sB;
        uint4 pre0, pre1;
        if (t<7){ pre0 = gg[(t+1)*1024 + tid]; pre1 = gg[(t+1)*1024 + tid + 512]; }
        int cwb = t*64 + nh*32 + (lane&3);
        uint32_t lwa[8], lwb[8];
        #pragma unroll
        for (int nt=0;nt<8;nt++){
            lwa[nt] = lg[lrowa + cwb + nt*4];
            lwb[nt] = lg[lrowb + cwb + nt*4];
        }
        uint32_t ek[4][4];
        #pragma unroll
        for (int nt=0;nt<8;nt++){
            float2 la = __half22float2(*(__half2*)&lwa[nt]);
            float2 lb = __half22float2(*(__half2*)&lwb[nt]);
            float e0 = expp(c1a*la.x);
            float e1 = expp(c1a*la.y);
            float e2 = expp(c1b*lb.x);
            float e3 = expp(c1b*lb.y);
            s3a += e0+e1; s3b += e2+e3;
            __nv_bfloat162 pa2 = __floats2bfloat162_rn(e0,e1);
            __nv_bfloat162 pb2 = __floats2bfloat162_rn(e2,e3);
            int kb = nt>>1, hh = (nt&1)<<1;
            ek[kb][hh]   = *(uint32_t*)&pa2;
            ek[kb][hh+1] = *(uint32_t*)&pb2;
        }
        #pragma unroll
        for (int kb=0;kb<4;kb++){
            #pragma unroll
            for (int np=0;np<4;np++){
                uint32_t bg[4];
                int gr = nh*64 + kb*16 + grow;
                ldsm4t(bg, curu + (uint32_t)((gr*72 + np*16 + gcol)*2));
                mma16816(Y[2*np], ek[kb], bg[0], bg[1]);
                mma16816(Y[2*np+1], ek[kb], bg[2], bg[3]);
            }
        }
        if (t<7){
            int i0 = tid;       *(uint4*)&nxt[(i0>>3)*72+(i0&7)*8] = pre0;
            i0 = tid + 512;     *(uint4*)&nxt[(i0>>3)*72+(i0&7)*8] = pre1;
        }
        __syncthreads();
    }
    s3a += __shfl_xor_sync(~0u,s3a,1); s3a += __shfl_xor_sync(~0u,s3a,2);
    s3b += __shfl_xor_sync(~0u,s3b,1); s3b += __shfl_xor_sync(~0u,s3b,2);
    if ((lane&3)==0){ ss3[nh][r0_] = s3a; ss3[nh][r1_] = s3b; }
    __nv_bfloat16 (*ysh)[68] = (__nv_bfloat16(*)[68])RAW;
    __nv_bfloat16 (*sYf)[72] = (__nv_bfloat16(*)[72])(RAW + 18432);
    __syncthreads();
    if (nh == 0){
        #pragma unroll
        for (int np2=0;np2<8;np2++){
            int c_ = np2*8 + colb;
            ysh[r0_][c_]   = __float2bfloat16(Y[np2][0]);
            ysh[r0_][c_+1] = __float2bfloat16(Y[np2][1]);
            ysh[r1_][c_]   = __float2bfloat16(Y[np2][2]);
            ysh[r1_][c_+1] = __float2bfloat16(Y[np2][3]);
        }
    }
    __syncthreads();
    if (nh == 1){
        float i3a = __fdividef(1.f, ss3[0][r0_] + ss3[1][r0_]);
        float i3b = __fdividef(1.f, ss3[0][r1_] + ss3[1][r1_]);
        #pragma unroll
        for (int np2=0;np2<8;np2++){
            int c_ = np2*8 + colb;
            __nv_bfloat162 va = __floats2bfloat162_rn(
                (Y[np2][0]+__bfloat162float(ysh[r0_][c_]))*i3a,
                (Y[np2][1]+__bfloat162float(ysh[r0_][c_+1]))*i3a);
            __nv_bfloat162 vb = __floats2bfloat162_rn(
                (Y[np2][2]+__bfloat162float(ysh[r1_][c_]))*i3b,
                (Y[np2][3]+__bfloat162float(ysh[r1_][c_+1]))*i3b);
            *(uint32_t*)&sYf[r0_][c_] = *(uint32_t*)&va;
            *(uint32_t*)&sYf[r1_][c_] = *(uint32_t*)&vb;
        }
    }
    __syncthreads();
    // fused z conv
    {
        uint32_t aWz[4][4];
        const __nv_bfloat16* w0 = g_zw_h + (qt*16 + ra)*64;
        const __nv_bfloat16* w8 = w0 + 8*64;
        #pragma unroll
        for (int kb=0;kb<4;kb++){
            int c0 = kb*16 + colb;
            aWz[kb][0] = *(const uint32_t*)&w0[c0];
            aWz[kb][1] = *(const uint32_t*)&w8[c0];
            aWz[kb][2] = *(const uint32_t*)&w0[c0+8];
            aWz[kb][3] = *(const uint32_t*)&w8[c0+8];
        }
        float accz[8][4];
        #pragma unroll
        for (int i=0;i<8;i++){ accz[i][0]=0.f;accz[i][1]=0.f;accz[i][2]=0.f;accz[i][3]=0.f; }
        #pragma unroll
        for (int kb=0;kb<4;kb++){
            #pragma unroll
            for (int ng=0;ng<4;ng++){
                uint32_t bq[4];
                ldsm4(bq, s2u(&sYf[nh*64 + ng*16 + brow][kb*16 + bcol]));
                mma16816(accz[2*ng], aWz[kb], bq[0], bq[1]);
                mma16816(accz[2*ng+1], aWz[kb], bq[2], bq[3]);
            }
        }
        float ba = zb[qt*16 + ra], bb = zb[qt*16 + ra + 8];
        float* zr0 = g_z + ((size_t)n*C + qt*16 + ra)*4096 + q0 + nh*64;
        float* zr8 = zr0 + 8*4096;
        #pragma unroll
        for (int ng=0;ng<4;ng++){
            #pragma unroll
            for (int j=0;j<2;j++){
                int px = ng*16 + j*8 + colb;
                *(float2*)&zr0[px] = make_float2(accz[2*ng+j][0]+ba, accz[2*ng+j][1]+ba);
                *(float2*)&zr8[px] = make_float2(accz[2*ng+j][2]+bb, accz[2*ng+j][3]+bb);
            }
        }
    }
}

// ---------- K6: epilogue ----------
__global__ void k_epi(const float* __restrict__ x, float* __restrict__ out){
    int idx = blockIdx.x*blockDim.x + threadIdx.x;
    if (idx >= NB*C*H0*H0/4) return;
    int xb4 = (idx & 63) << 2;
    int Y = (idx>>6) & 255;
    int nch = idx >> 14;
    float sy = (float)(Y*63)/255.f;
    int yl=(int)sy; int yh=min(yl+1,63); float fy=sy-yl;
    const float* z0 = g_z + (size_t)nch*4096 + yl*64;
    const float* z1 = g_z + (size_t)nch*4096 + yh*64;
    float4 r;
    float* rp = &r.x;
    #pragma unroll
    for (int k=0;k<4;k++){
        int X_ = xb4 + k;
        float sx = (float)(X_*63)/255.f;
        int xl=(int)sx; int xh=min(xl+1,63); float fx=sx-xl;
        rp[k] = (z0[xl]*(1.f-fx)+z0[xh]*fx)*(1.f-fy)
              + (z1[xl]*(1.f-fx)+z1[xh]*fx)*fy;
    }
    float4 xin = *(const float4*)(x + ((size_t)idx<<2));
    r.x += xin.x; r.y += xin.y; r.z += xin.z; r.w += xin.w;
    *(float4*)(out + ((size_t)idx<<2)) = r;
}

// ---------- host ----------
extern "C" void kernel_launch(void* const* d_in, const int* in_sizes, int n_in,
                              void* d_out, int out_size){
    const float* x       = (const float*)d_in[0];
    const float* depth   = (const float*)d_in[1];
    const float* down_w  = (const float*)d_in[2];
    const float* theta_w = (const float*)d_in[3];
    const float* theta_b = (const float*)d_in[4];
    const float* phi_w   = (const float*)d_in[5];
    const float* phi_b   = (const float*)d_in[6];
    const float* g_w     = (const float*)d_in[7];
    const float* g_b     = (const float*)d_in[8];
    const float* z_w     = (const float*)d_in[9];
    const float* z_b     = (const float*)d_in[10];
    const float* ppg_pw  = (const float*)d_in[11];
    const float* ppg_gam = (const float*)d_in[12];
    const float* ppg_bet = (const float*)d_in[13];
    const float* ppg_ow  = (const float*)d_in[14];
    const float* ppg_ob  = (const float*)d_in[15];
    const float* ppt_pw  = (const float*)d_in[16];
    const float* ppt_gam = (const float*)d_in[17];
    const float* ppt_bet = (const float*)d_in[18];
    const float* ppt_ow  = (const float*)d_in[19];
    const float* ppt_ob  = (const float*)d_in[20];
    const float* ppp_pw  = (const float*)d_in[21];
    const float* ppp_gam = (const float*)d_in[22];
    const float* ppp_bet = (const float*)d_in[23];
    const float* ppp_ow  = (const float*)d_in[24];
    const float* ppp_ob  = (const float*)d_in[25];
    float* out = (float*)d_out;

    k_prep<<<(7*8192 + 255)/256, 256>>>(theta_w, g_w, phi_w, z_w, ppg_ow, ppt_ow, ppp_ow);
    k_convs_hmma<<<NB*32, 384>>>(x, down_w, theta_b, g_b, phi_b);
    k_pool_all<<<3*NB*64, 256>>>();
    k_levelconv_all<<<(3*NB*85*16 + 63)/64, 64>>>(ppg_pw, ppg_gam, ppg_bet,
                                                  ppt_pw, ppt_gam, ppt_bet,
                                                  ppp_pw, ppp_gam, ppp_bet);
    k_ppfinal_all<<<384, 256>>>(ppg_ob, ppt_ob, ppp_ob);
    k_attn_hmma<<<NB*32, 512>>>(depth, z_b);
    k_epi<<<(NB*C*H0*H0/4 + 255)/256, 256>>>(x, out);
}

// round 15
// speedup vs baseline: 1.0122x; 1.0122x over previous
#include <cuda_runtime.h>
#include <cuda_bf16.h>
#include <cuda_fp16.h>
#include <math.h>
#include <cstdint>

#define NB 4
#define C 128
#define CC 64
#define H0 256
#define HD 64
#define EPS6 1e-6f
#define BN_INV 0.9999950000374997f
#define E1F 2.7182818284590452f

// ---------- helpers ----------
__device__ __forceinline__ uint32_t s2u(const void* p){
    uint32_t a; asm("{ .reg .u64 t; cvta.to.shared.u64 t, %1; cvt.u32.u64 %0, t; }" : "=r"(a) : "l"(p)); return a;
}
__device__ __forceinline__ void ldsm4(uint32_t* r, uint32_t a){
    asm volatile("ldmatrix.sync.aligned.m8n8.x4.shared.b16 {%0,%1,%2,%3}, [%4];"
        : "=r"(r[0]),"=r"(r[1]),"=r"(r[2]),"=r"(r[3]) : "r"(a));
}
__device__ __forceinline__ void ldsm4t(uint32_t* r, uint32_t a){
    asm volatile("ldmatrix.sync.aligned.m8n8.x4.trans.shared.b16 {%0,%1,%2,%3}, [%4];"
        : "=r"(r[0]),"=r"(r[1]),"=r"(r[2]),"=r"(r[3]) : "r"(a));
}
__device__ __forceinline__ void mma16816(float* d, const uint32_t* a, uint32_t b0, uint32_t b1){
    asm volatile("mma.sync.aligned.m16n8k16.row.col.f32.bf16.bf16.f32 "
        "{%0,%1,%2,%3}, {%4,%5,%6,%7}, {%8,%9}, {%0,%1,%2,%3};"
        : "+f"(d[0]),"+f"(d[1]),"+f"(d[2]),"+f"(d[3])
        : "r"(a[0]),"r"(a[1]),"r"(a[2]),"r"(a[3]), "r"(b0),"r"(b1));
}
// exp(x) for x in [0, 1.2]: half-and-square Taylor deg 6, rel err < 6e-6. Pure FMA.
__device__ __forceinline__ float expp(float x){
    float h = 0.5f*x;
    float p = __fmaf_rn(h, 0.0013888889f, 0.0083333333f);
    p = __fmaf_rn(h, p, 0.0416666667f);
    p = __fmaf_rn(h, p, 0.1666666667f);
    p = __fmaf_rn(h, p, 0.5f);
    p = __fmaf_rn(h, p, 1.0f);
    p = __fmaf_rn(h, p, 1.0f);
    return p*p;
}
__device__ __forceinline__ float sum8bf(uint4 v){
    const __nv_bfloat162* h = (const __nv_bfloat162*)&v;
    float s = 0.f;
    #pragma unroll
    for (int i=0;i<4;i++){ float2 f = __bfloat1622float2(h[i]); s += f.x + f.y; }
    return s;
}

// ---------- scratch ----------
__device__ __align__(16) __nv_bfloat16 g_xd_h[NB*C*4096];
__device__ __align__(16) __nv_bfloat16 g_wcat[192*128];
__device__ __align__(16) __nv_bfloat16 g_zw_h[128*64];
__device__ __align__(16) __nv_bfloat16 g_owcat[3*64*128];
__device__ __align__(16) __nv_bfloat16 g_thin [NB*CC*HD*HD];
__device__ __align__(16) __nv_bfloat16 g_g0   [NB*CC*1024];
__device__ __align__(16) __nv_bfloat16 g_phi0 [NB*CC*1024];
__device__ float g_poolT[3*NB*85*64];
__device__ float g_ppc  [3][NB*85*16];
__device__ __align__(16) __nv_bfloat16 g_th_h [NB*4096*64];
__device__ __align__(16) __nv_bfloat16 g_phi_h[NB*1024*64];
__device__ __align__(16) __nv_bfloat16 g_gv_h [NB*1024*64];
__device__ uint32_t g_lg[NB*4096*512];
__device__ float g_z[NB*C*4096];

// ---------- K1: down conv -> bf16, fused weight prep (wide grid) ----------
__global__ void k_down(const float* __restrict__ x, const float* __restrict__ dw,
                       const float* __restrict__ tw, const float* __restrict__ gw,
                       const float* __restrict__ pw, const float* __restrict__ zw,
                       const float* __restrict__ ow0, const float* __restrict__ ow1,
                       const float* __restrict__ ow2){
    int idx = blockIdx.x*256 + threadIdx.x;
    if (idx < NB*C*HD*HD){
        int j = idx & 63, i = (idx>>6) & 63, nc = idx>>12;
        int ch = nc & (C-1);
        const float* xb = x + ((size_t)nc<<16) + i*4*256 + j*4;
        const float* w = dw + ch*16;
        float s = 0.f;
        #pragma unroll
        for (int a=0; a<4; a++){
            float4 v = *(const float4*)(xb + a*256);
            s += v.x*w[a*4+0] + v.y*w[a*4+1] + v.z*w[a*4+2] + v.w*w[a*4+3];
        }
        g_xd_h[idx] = __float2bfloat16(s);
    } else {
        int i = idx - NB*C*HD*HD;
        if (i < 3*8192){
            int m = i >> 13;
            const float* src = (m==0) ? tw : (m==1) ? gw : pw;
            g_wcat[i] = __float2bfloat16(src[i & 8191]);
        } else if (i < 4*8192){
            g_zw_h[i - 3*8192] = __float2bfloat16(zw[i - 3*8192]);
        } else if (i < 7*8192){
            int m = (i - 4*8192) >> 13;
            const float* src = (m==0) ? ow0 : (m==1) ? ow1 : ow2;
            g_owcat[i - 4*8192] = __float2bfloat16(src[(i - 4*8192) & 8191]);
        }
    }
}

// ---------- K2: theta/g/phi convs via HMMA, maxpool fused ----------
__global__ void __launch_bounds__(384) k_convs_hmma(const float* __restrict__ tb_,
                        const float* __restrict__ gb_, const float* __restrict__ pb_){
    __shared__ __nv_bfloat16 sX[2][128][72];
    int tid = threadIdx.x, w = tid>>5, lane = tid&31;
    int n = blockIdx.x >> 5;
    int tb = blockIdx.x & 31;
    int px0 = tb * 128;
    const __nv_bfloat16* xsrc = g_xd_h + (size_t)n*C*4096;

    int r = lane>>2, cq = (lane&3)*2;
    uint32_t aW[8][4];
    {
        const __nv_bfloat16* w0 = g_wcat + (w*16 + r)*128;
        const __nv_bfloat16* w8 = w0 + 8*128;
        #pragma unroll
        for (int kb=0;kb<8;kb++){
            int c0 = kb*16 + cq;
            aW[kb][0] = *(const uint32_t*)&w0[c0];
            aW[kb][1] = *(const uint32_t*)&w8[c0];
            aW[kb][2] = *(const uint32_t*)&w0[c0+8];
            aW[kb][3] = *(const uint32_t*)&w8[c0+8];
        }
    }
    for (int i=tid; i<2048; i+=384){
        int buf = i>>10, rem = i&1023;
        int c = rem>>3, p = (rem&7)*8;
        *(uint4*)&sX[buf][c][p] = *(const uint4*)&xsrc[c*4096 + px0 + buf*64 + p];
    }
    __syncthreads();

    int grow = (lane&7) + ((lane&8)?8:0);
    int gcol = (lane&16)?8:0;
    int brn = w >> 2, o0 = (w&3)*16;
    const float* bias = (brn==0) ? tb_ : (brn==1) ? gb_ : pb_;
    float ba = bias[o0 + r], bb = bias[o0 + r + 8];
    int colb = (lane&3)*2;

    float hm0[2][8], hm8[2][8];
    __nv_bfloat16* row0 = g_thin + ((size_t)n*CC + o0 + r)*4096 + px0;
    __nv_bfloat16* row8 = row0 + 8*4096;

    #pragma unroll
    for (int t=0;t<2;t++){
        float acc[8][4];
        #pragma unroll
        for (int i=0;i<8;i++){ acc[i][0]=0.f;acc[i][1]=0.f;acc[i][2]=0.f;acc[i][3]=0.f; }
        #pragma unroll
        for (int kb=0;kb<8;kb++){
            int kr = kb*16 + grow;
            #pragma unroll
            for (int np=0;np<4;np++){
                uint32_t bg[4];
                ldsm4t(bg, s2u(&sX[t][kr][np*16 + gcol]));
                mma16816(acc[2*np], aW[kb], bg[0], bg[1]);
                mma16816(acc[2*np+1], aW[kb], bg[2], bg[3]);
            }
        }
        if (brn == 0){
            #pragma unroll
            for (int nf=0;nf<8;nf++){
                int px = t*64 + nf*8 + colb;
                __nv_bfloat162 v0 = __floats2bfloat162_rn(acc[nf][0]+ba, acc[nf][1]+ba);
                __nv_bfloat162 v8 = __floats2bfloat162_rn(acc[nf][2]+bb, acc[nf][3]+bb);
                *(uint32_t*)&row0[px] = *(uint32_t*)&v0;
                *(uint32_t*)&row8[px] = *(uint32_t*)&v8;
            }
        } else {
            #pragma unroll
            for (int nf=0;nf<8;nf++){
                hm0[t][nf] = fmaxf(acc[nf][0], acc[nf][1]);
                hm8[t][nf] = fmaxf(acc[nf][2], acc[nf][3]);
            }
        }
    }
    if (brn != 0){
        __nv_bfloat16* dst = ((brn==1) ? g_g0 : g_phi0) + ((size_t)n*CC + o0 + r)*1024 + tb*32;
        int vx = lane&3;
        #pragma unroll
        for (int nf=0;nf<8;nf++){
            dst[nf*4 + vx]          = __float2bfloat16(fmaxf(hm0[0][nf], hm0[1][nf]) + ba);
            dst[8*1024 + nf*4 + vx] = __float2bfloat16(fmaxf(hm8[0][nf], hm8[1][nf]) + bb);
        }
    }
}

// ---------- K3: pyramid pools (bf16 in, fp32 out transposed) ----------
__global__ void __launch_bounds__(256) k_pool_all(){
    __shared__ float sp[4][64];
    __shared__ float s8[64], s4[16], s2[4];
    int bid = blockIdx.x;
    int br = bid >> 8; int nc = bid & 255;
    int n = nc >> 6, c = nc & 63;
    int bn = br*NB + n;
    int H = (br==1) ? 64 : 32;
    const __nv_bfloat16* in = (br==0) ? g_g0 : (br==1) ? g_thin : g_phi0;
    const __nv_bfloat16* p = in + (size_t)nc*H*H;
    int t = threadIdx.x & 63, q = threadIdx.x >> 6;
    int k0 = H >> 3;
    int cy = t>>3, cx = t&7;
    const __nv_bfloat16* cell = p + (cy*k0)*H + cx*k0;
    float s = 0.f;
    if (k0 == 8){
        #pragma unroll
        for (int a=0;a<2;a++){
            const uint4* rp = (const uint4*)(cell + (q*2+a)*H);
            s += sum8bf(rp[0]);
        }
    } else {
        const __nv_bfloat162* hp = (const __nv_bfloat162*)(cell + q*H);
        float2 f0 = __bfloat1622float2(hp[0]);
        float2 f1 = __bfloat1622float2(hp[1]);
        s = f0.x+f0.y+f1.x+f1.y;
    }
    sp[q][t] = s;
    __syncthreads();
    float* ob = g_poolT + (size_t)bn*85*64 + c;
    if (threadIdx.x < 64){
        float tot = sp[0][threadIdx.x]+sp[1][threadIdx.x]+sp[2][threadIdx.x]+sp[3][threadIdx.x];
        s8[threadIdx.x] = tot;
        ob[threadIdx.x*64] = tot / (float)(k0*k0);
    }
    __syncthreads();
    if (threadIdx.x < 16){
        int tt = threadIdx.x;
        int yy=tt>>2, xx=tt&3;
        float v = s8[(2*yy)*8+2*xx] + s8[(2*yy)*8+2*xx+1] + s8[(2*yy+1)*8+2*xx] + s8[(2*yy+1)*8+2*xx+1];
        s4[tt]=v; ob[(64+tt)*64] = v / (float)(4*k0*k0);
    }
    __syncthreads();
    if (threadIdx.x < 4){
        int tt = threadIdx.x;
        int yy=tt>>1, xx=tt&1;
        float v = s4[(2*yy)*4+2*xx] + s4[(2*yy)*4+2*xx+1] + s4[(2*yy+1)*4+2*xx] + s4[(2*yy+1)*4+2*xx+1];
        s2[tt]=v; ob[(80+tt)*64] = v / (float)(16*k0*k0);
    }
    __syncthreads();
    if (threadIdx.x == 0) ob[84*64] = (s2[0]+s2[1]+s2[2]+s2[3]) / (float)(64*k0*k0);
}

// ---------- K4: level convs, 8 threads/output + shfl reduce ----------
__global__ void k_levelconv_all(const float* __restrict__ pw0, const float* __restrict__ g0, const float* __restrict__ b0,
                                const float* __restrict__ pw1, const float* __restrict__ g1, const float* __restrict__ b1,
                                const float* __restrict__ pw2, const float* __restrict__ g2, const float* __restrict__ b2){
    int gidx = blockIdx.x*blockDim.x + threadIdx.x;
    if (gidx >= 3*NB*85*16*8) return;
    int j = gidx & 7;
    int idx = gidx >> 3;
    int o = idx & 15;
    int s = (idx>>4) % 85;
    int bn = idx / (85*16);
    int br = bn >> 2, nn = bn & 3;
    const float* pw = (br==0)?pw0:(br==1)?pw1:pw2;
    const float* gamma = (br==0)?g0:(br==1)?g1:g2;
    const float* beta = (br==0)?b0:(br==1)?b1:b2;
    int lvl = (s<64) ? 0 : (s<80 ? 1 : (s<84 ? 2 : 3));
    const float4* w4 = (const float4*)(pw + (lvl*16+o)*64) + j*2;
    const float4* p4 = (const float4*)(g_poolT + (size_t)bn*85*64 + s*64) + j*2;
    float acc = 0.f;
    #pragma unroll
    for (int i=0;i<2;i++){
        float4 a = __ldg(&w4[i]);
        float4 b = p4[i];
        acc += a.x*b.x + a.y*b.y + a.z*b.z + a.w*b.w;
    }
    acc += __shfl_xor_sync(~0u, acc, 1);
    acc += __shfl_xor_sync(~0u, acc, 2);
    acc += __shfl_xor_sync(~0u, acc, 4);
    if (j == 0){
        acc = acc*BN_INV*__ldg(&gamma[lvl*16+o]) + __ldg(&beta[lvl*16+o]);
        g_ppc[br][(nn*85+s)*16+o] = fmaxf(acc, 0.f);
    }
}

// ---------- K5: pyramid final convs via HMMA ----------
__global__ void __launch_bounds__(256) k_ppfinal_all(
        const float* __restrict__ ob0, const float* __restrict__ ob1, const float* __restrict__ ob2){
    __shared__ __nv_bfloat16 sB[128][72];
    __shared__ __nv_bfloat16 sO[64][72];
    __shared__ float spp[85*16];
    int bid = blockIdx.x;
    int br, n, t0;
    if (bid < 256){ br = 1; n = bid>>6; t0 = (bid&63)<<6; }
    else {
        int r = bid - 256;
        br = (r < 64) ? 0 : 2;
        int r2 = r & 63;
        n = r2 >> 4; t0 = (r2 & 15) << 6;
    }
    const float* ob = (br==0)?ob0:(br==1)?ob1:ob2;
    int H = (br==1) ? 64 : 32;
    int P = H*H;
    const __nv_bfloat16* X = (br==0) ? g_g0 : (br==1) ? g_thin : g_phi0;
    const __nv_bfloat16* xin = X + (size_t)n*CC*P;
    int tid = threadIdx.x, w = tid>>5, lane = tid&31;
    for (int i=tid; i<512; i+=256){
        int c = i>>3, p8 = (i&7)*8;
        *(uint4*)&sB[c][p8] = *(const uint4*)&xin[c*P + t0 + p8];
    }
    for (int i=tid; i<1360; i+=256) spp[i] = g_ppc[br][n*1360 + i];
    __syncthreads();
    float invH = 1.0f / (float)H;
    for (int e = tid; e < 4096; e += 256){
        int u = e>>6, p = e&63;
        int lvl = u>>4, j = u&15;
        int pix = t0 + p; int y = pix / H, x = pix % H;
        int ps = 8 >> lvl;
        int off = (lvl==0) ? 0 : (lvl==1 ? 64 : (lvl==2 ? 80 : 84));
        float sy = fminf(fmaxf((y+0.5f)*ps*invH - 0.5f, 0.f), (float)(ps-1));
        float sx = fminf(fmaxf((x+0.5f)*ps*invH - 0.5f, 0.f), (float)(ps-1));
        int yl=(int)sy; int yh=min(yl+1, ps-1); float fy=sy-yl;
        int xl=(int)sx; int xh=min(xl+1, ps-1); float fx=sx-xl;
        const float* b00 = spp + (off + yl*ps + xl)*16;
        const float* b01 = spp + (off + yl*ps + xh)*16;
        const float* b10 = spp + (off + yh*ps + xl)*16;
        const float* b11 = spp + (off + yh*ps + xh)*16;
        float v = (b00[j]*(1.f-fx)+b01[j]*fx)*(1.f-fy) + (b10[j]*(1.f-fx)+b11[j]*fx)*fy;
        sB[64+u][p] = __float2bfloat16(v);
    }
    __syncthreads();
    int mt = w & 3, ph = w >> 2;
    int ra = lane>>2, colb = (lane&3)*2, cq = (lane&3)*2;
    uint32_t aW[8][4];
    {
        const __nv_bfloat16* w0 = g_owcat + br*8192 + (mt*16 + ra)*128;
        const __nv_bfloat16* w8 = w0 + 8*128;
        #pragma unroll
        for (int kb=0;kb<8;kb++){
            int c0 = kb*16 + cq;
            aW[kb][0] = *(const uint32_t*)&w0[c0];
            aW[kb][1] = *(const uint32_t*)&w8[c0];
            aW[kb][2] = *(const uint32_t*)&w0[c0+8];
            aW[kb][3] = *(const uint32_t*)&w8[c0+8];
        }
    }
    int grow = (lane&7) + ((lane&8)?8:0);
    int gcol = (lane&16)?8:0;
    float acc[4][4];
    #pragma unroll
    for (int i=0;i<4;i++){ acc[i][0]=0.f;acc[i][1]=0.f;acc[i][2]=0.f;acc[i][3]=0.f; }
    #pragma unroll
    for (int kb=0;kb<8;kb++){
        int kr = kb*16 + grow;
        #pragma unroll
        for (int np=0;np<2;np++){
            uint32_t bg[4];
            ldsm4t(bg, s2u(&sB[kr][ph*32 + np*16 + gcol]));
            mma16816(acc[2*np], aW[kb], bg[0], bg[1]);
            mma16816(acc[2*np+1], aW[kb], bg[2], bg[3]);
        }
    }
    float ba = ob[mt*16 + ra], bb = ob[mt*16 + ra + 8];
    #pragma unroll
    for (int nf=0;nf<4;nf++){
        int px = ph*32 + (nf>>1)*16 + (nf&1)*8 + colb;
        sO[px][mt*16+ra]     = __float2bfloat16(acc[nf][0]+ba);
        sO[px+1][mt*16+ra]   = __float2bfloat16(acc[nf][1]+ba);
        sO[px][mt*16+ra+8]   = __float2bfloat16(acc[nf][2]+bb);
        sO[px+1][mt*16+ra+8] = __float2bfloat16(acc[nf][3]+bb);
    }
    __syncthreads();
    __nv_bfloat16* dst = (br==1) ? (g_th_h + ((size_t)n*4096 + t0)*64)
                      : (br==0) ? (g_gv_h + ((size_t)n*1024 + t0)*64)
                                : (g_phi_h + ((size_t)n*1024 + t0)*64);
    for (int i=tid; i<512; i+=256){
        int px = i>>3, o8 = (i&7)*8;
        *(uint4*)&dst[px*64 + o8] = *(const uint4*)&sO[px][o8];
    }
}

// ---------- bilinear on 256x256 ----------
__device__ __forceinline__ float bil256(const float* p, float sy, float sx){
    int yl=(int)sy; int yh=min(yl+1,255); float fy=sy-yl;
    int xl=(int)sx; int xh=min(xl+1,255); float fx=sx-xl;
    return (p[yl*256+xl]*(1.f-fx)+p[yl*256+xh]*fx)*(1.f-fy)
         + (p[yh*256+xl]*(1.f-fx)+p[yh*256+xh]*fx)*fy;
}

// ---------- K6: HMMA attention + fused z-conv epilogue ----------
__global__ void __launch_bounds__(512,1) k_attn_hmma(const float* __restrict__ depth,
                                                     const float* __restrict__ zb){
    __shared__ __align__(16) char RAW[36864];
    __shared__ float2 d2s[1024];
    __shared__ float d1s[128];
    __shared__ float ss3[2][128];
    __nv_bfloat16* sA = (__nv_bfloat16*)RAW;
    __nv_bfloat16* sB = (__nv_bfloat16*)(RAW + 18432);
    float* STF = (float*)RAW;
    int tid = threadIdx.x, w = tid>>5, lane = tid&31;
    int qt = w & 7, nh = w >> 3;
    int n = blockIdx.x>>5, q0 = (blockIdx.x&31)*128;

    const float* dm = depth + (size_t)n*65536;
    for (int i=tid;i<1024;i+=512){
        int yy=i>>5, xx=i&31;
        float d2 = bil256(dm, (float)(yy*255)/31.f, (float)(xx*255)/31.f);
        d2s[i] = make_float2(d2, __fdividef(1.f, d2+EPS6));
    }
    if (tid < 128){
        int q = q0 + tid;
        d1s[tid] = bil256(dm, (float)((q>>6)*255)/63.f, (float)((q&63)*255)/63.f);
    }
    const uint4* qg = (const uint4*)(g_th_h + ((size_t)(n*4096+q0))*64);
    for (int i=tid;i<1024;i+=512)
        *(uint4*)&sA[(i>>3)*72 + (i&7)*8] = qg[i];
    __syncthreads();
    uint32_t sAu = s2u(sA), sBu = s2u(sB);
    uint32_t aQ[4][4];
    {
        int arow = qt*16 + (lane&15);
        int acol = (lane>>4)<<3;
        #pragma unroll
        for (int kb=0;kb<4;kb++)
            ldsm4(aQ[kb], sAu + (uint32_t)((arow*72 + kb*16 + acol)*2));
    }
    int ra = lane>>2, colb = (lane&3)*2;
    int r0_ = qt*16 + ra, r1_ = r0_ + 8;
    float d1a = d1s[r0_], d1b = d1s[r1_];
    float ir1a = __fdividef(1.f,d1a+EPS6), ir1b = __fdividef(1.f,d1b+EPS6);
    __syncthreads();

    int brow = (lane&7) + ((lane&16)?8:0);
    int bcol = (lane&8)?8:0;
    int grow = (lane&7) + ((lane&8)?8:0);
    int gcol = (lane&16)?8:0;
    const uint4* phg = (const uint4*)(g_phi_h + (size_t)n*65536);
    const uint4* gg  = (const uint4*)(g_gv_h + (size_t)n*65536);
    uint32_t* lg = g_lg + ((size_t)(n*4096 + q0))*512;
    int lrowa = r0_*512, lrowb = r1_*512;

    float s1a=0.f, s2a=0.f, s1b=0.f, s2b=0.f;

    for (int i=tid;i<1024;i+=512)
        *(uint4*)&sA[(i>>3)*72+(i&7)*8] = phg[i];
    __syncthreads();

    // ===== pass 1 =====
    for (int t=0;t<8;t++){
        uint32_t curu = (t&1) ? sBu : sAu;
        __nv_bfloat16* nxt = (t&1) ? sA : sB;
        uint4 pre0, pre1;
        if (t<7){ pre0 = phg[(t+1)*1024 + tid]; pre1 = phg[(t+1)*1024 + tid + 512]; }
        float L[8][4];
        #pragma unroll
        for (int nt=0;nt<8;nt++){ L[nt][0]=0.f;L[nt][1]=0.f;L[nt][2]=0.f;L[nt][3]=0.f; }
        #pragma unroll
        for (int kb=0;kb<4;kb++){
            #pragma unroll
            for (int ng=0;ng<4;ng++){
                uint32_t bq[4];
                int br_ = nh*64 + ng*16 + brow;
                ldsm4(bq, curu + (uint32_t)((br_*72 + kb*16 + bcol)*2));
                mma16816(L[2*ng], aQ[kb], bq[0], bq[1]);
                mma16816(L[2*ng+1], aQ[kb], bq[2], bq[3]);
            }
        }
        if (t<7){
            int i0 = tid;       *(uint4*)&nxt[(i0>>3)*72+(i0&7)*8] = pre0;
            i0 = tid + 512;     *(uint4*)&nxt[(i0>>3)*72+(i0&7)*8] = pre1;
        }
        int cwb = t*64 + nh*32 + (lane&3);
        #pragma unroll
        for (int nt=0;nt<8;nt++){
            int v = t*128 + nh*64 + nt*8 + colb;
            float2 dp = d2s[v], dq = d2s[v+1];
            float r0 = fminf(d1a*dp.y, dp.x*ir1a);
            float r1 = fminf(d1a*dq.y, dq.x*ir1a);
            float r2 = fminf(d1b*dp.y, dp.x*ir1b);
            float r3 = fminf(d1b*dq.y, dq.x*ir1b);
            s2a += __expf(r0-1.f) + __expf(r1-1.f);
            s2b += __expf(r2-1.f) + __expf(r3-1.f);
            s1a += __expf(L[nt][0]) + __expf(L[nt][1]);
            s1b += __expf(L[nt][2]) + __expf(L[nt][3]);
            __half2 ha = __floats2half2_rn(__expf(L[nt][0]+r0), __expf(L[nt][1]+r1));
            __half2 hb = __floats2half2_rn(__expf(L[nt][2]+r2), __expf(L[nt][3]+r3));
            lg[lrowa + cwb + nt*4] = *(uint32_t*)&ha;
            lg[lrowb + cwb + nt*4] = *(uint32_t*)&hb;
        }
        __syncthreads();
    }

    #pragma unroll
    for (int o=1;o<=2;o<<=1){
        s1a += __shfl_xor_sync(~0u,s1a,o);
        s1b += __shfl_xor_sync(~0u,s1b,o);
        s2a += __shfl_xor_sync(~0u,s2a,o);
        s2b += __shfl_xor_sync(~0u,s2b,o);
    }
    if ((lane&3)==0){
        STF[      nh*128 + r0_] = s1a;  STF[      nh*128 + r1_] = s1b;
        STF[256 + nh*128 + r0_] = s2a;  STF[256 + nh*128 + r1_] = s2b;
    }
    __syncthreads();
    float S1a = STF[r0_] + STF[128+r0_];
    float S2a = (STF[256+r0_] + STF[256+128+r0_]) * E1F;
    float S1b = STF[r1_] + STF[128+r1_];
    float S2b = (STF[256+r1_] + STF[256+128+r1_]) * E1F;
    float c1a = __fdividef(1.f, S1a*S2a);
    float c1b = __fdividef(1.f, S1b*S2b);
    __syncthreads();

    // ===== pass 2 =====
    float Y[8][4];
    #pragma unroll
    for (int i=0;i<8;i++){ Y[i][0]=0.f;Y[i][1]=0.f;Y[i][2]=0.f;Y[i][3]=0.f; }
    float s3a=0.f, s3b=0.f;
    for (int i=tid;i<1024;i+=512)
        *(uint4*)&sA[(i>>3)*72+(i&7)*8] = gg[i];
    __syncthreads();
    for (int t=0;t<8;t++){
        uint32_t curu = (t&1) ? sBu : sAu;
        __nv_bfloat16* nxt = (t&1) ? sA : sB;
        uint4 pre0, pre1;
        if (t<7){ pre0 = gg[(t+1)*1024 + tid]; pre1 = gg[(t+1)*1024 + tid + 512]; }
        int cwb = t*64 + nh*32 + (lane&3);
        uint32_t lwa[8], lwb[8];
        #pragma unroll
        for (int nt=0;nt<8;nt++){
            lwa[nt] = lg[lrowa + cwb + nt*4];
            lwb[nt] = lg[lrowb + cwb + nt*4];
        }
        uint32_t ek[4][4];
        #pragma unroll
        for (int nt=0;nt<8;nt++){
            float2 la = __half22float2(*(__half2*)&lwa[nt]);
            float2 lb = __half22float2(*(__half2*)&lwb[nt]);
            float e0 = expp(c1a*la.x);
            float e1 = expp(c1a*la.y);
            float e2 = expp(c1b*lb.x);
            float e3 = expp(c1b*lb.y);
            s3a += e0+e1; s3b += e2+e3;
            __nv_bfloat162 pa2 = __floats2bfloat162_rn(e0,e1);
            __nv_bfloat162 pb2 = __floats2bfloat162_rn(e2,e3);
            int kb = nt>>1, hh = (nt&1)<<1;
            ek[kb][hh]   = *(uint32_t*)&pa2;
            ek[kb][hh+1] = *(uint32_t*)&pb2;
        }
        #pragma unroll
        for (int kb=0;kb<4;kb++){
            #pragma unroll
            for (int np=0;np<4;np++){
                uint32_t bg[4];
                int gr = nh*64 + kb*16 + grow;
                ldsm4t(bg, curu + (uint32_t)((gr*72 + np*16 + gcol)*2));
                mma16816(Y[2*np], ek[kb], bg[0], bg[1]);
                mma16816(Y[2*np+1], ek[kb], bg[2], bg[3]);
            }
        }
        if (t<7){
            int i0 = tid;       *(uint4*)&nxt[(i0>>3)*72+(i0&7)*8] = pre0;
            i0 = tid + 512;     *(uint4*)&nxt[(i0>>3)*72+(i0&7)*8] = pre1;
        }
        __syncthreads();
    }
    s3a += __shfl_xor_sync(~0u,s3a,1); s3a += __shfl_xor_sync(~0u,s3a,2);
    s3b += __shfl_xor_sync(~0u,s3b,1); s3b += __shfl_xor_sync(~0u,s3b,2);
    if ((lane&3)==0){ ss3[nh][r0_] = s3a; ss3[nh][r1_] = s3b; }
    __nv_bfloat16 (*ysh)[68] = (__nv_bfloat16(*)[68])RAW;
    __nv_bfloat16 (*sYf)[72] = (__nv_bfloat16(*)[72])(RAW + 18432);
    __syncthreads();
    if (nh == 0){
        #pragma unroll
        for (int np2=0;np2<8;np2++){
            int c_ = np2*8 + colb;
            ysh[r0_][c_]   = __float2bfloat16(Y[np2][0]);
            ysh[r0_][c_+1] = __float2bfloat16(Y[np2][1]);
            ysh[r1_][c_]   = __float2bfloat16(Y[np2][2]);
            ysh[r1_][c_+1] = __float2bfloat16(Y[np2][3]);
        }
    }
    __syncthreads();
    if (nh == 1){
        float i3a = __fdividef(1.f, ss3[0][r0_] + ss3[1][r0_]);
        float i3b = __fdividef(1.f, ss3[0][r1_] + ss3[1][r1_]);
        #pragma unroll
        for (int np2=0;np2<8;np2++){
            int c_ = np2*8 + colb;
            __nv_bfloat162 va = __floats2bfloat162_rn(
                (Y[np2][0]+__bfloat162float(ysh[r0_][c_]))*i3a,
                (Y[np2][1]+__bfloat162float(ysh[r0_][c_+1]))*i3a);
            __nv_bfloat162 vb = __floats2bfloat162_rn(
                (Y[np2][2]+__bfloat162float(ysh[r1_][c_]))*i3b,
                (Y[np2][3]+__bfloat162float(ysh[r1_][c_+1]))*i3b);
            *(uint32_t*)&sYf[r0_][c_] = *(uint32_t*)&va;
            *(uint32_t*)&sYf[r1_][c_] = *(uint32_t*)&vb;
        }
    }
    __syncthreads();
    // fused z conv
    {
        uint32_t aWz[4][4];
        const __nv_bfloat16* w0 = g_zw_h + (qt*16 + ra)*64;
        const __nv_bfloat16* w8 = w0 + 8*64;
        #pragma unroll
        for (int kb=0;kb<4;kb++){
            int c0 = kb*16 + colb;
            aWz[kb][0] = *(const uint32_t*)&w0[c0];
            aWz[kb][1] = *(const uint32_t*)&w8[c0];
            aWz[kb][2] = *(const uint32_t*)&w0[c0+8];
            aWz[kb][3] = *(const uint32_t*)&w8[c0+8];
        }
        float accz[8][4];
        #pragma unroll
        for (int i=0;i<8;i++){ accz[i][0]=0.f;accz[i][1]=0.f;accz[i][2]=0.f;accz[i][3]=0.f; }
        #pragma unroll
        for (int kb=0;kb<4;kb++){
            #pragma unroll
            for (int ng=0;ng<4;ng++){
                uint32_t bq[4];
                ldsm4(bq, s2u(&sYf[nh*64 + ng*16 + brow][kb*16 + bcol]));
                mma16816(accz[2*ng], aWz[kb], bq[0], bq[1]);
                mma16816(accz[2*ng+1], aWz[kb], bq[2], bq[3]);
            }
        }
        float ba = zb[qt*16 + ra], bb = zb[qt*16 + ra + 8];
        float* zr0 = g_z + ((size_t)n*C + qt*16 + ra)*4096 + q0 + nh*64;
        float* zr8 = zr0 + 8*4096;
        #pragma unroll
        for (int ng=0;ng<4;ng++){
            #pragma unroll
            for (int j=0;j<2;j++){
                int px = ng*16 + j*8 + colb;
                *(float2*)&zr0[px] = make_float2(accz[2*ng+j][0]+ba, accz[2*ng+j][1]+ba);
                *(float2*)&zr8[px] = make_float2(accz[2*ng+j][2]+bb, accz[2*ng+j][3]+bb);
            }
        }
    }
}

// ---------- K7: epilogue ----------
__global__ void k_epi(const float* __restrict__ x, float* __restrict__ out){
    int idx = blockIdx.x*blockDim.x + threadIdx.x;
    if (idx >= NB*C*H0*H0/4) return;
    int xb4 = (idx & 63) << 2;
    int Y = (idx>>6) & 255;
    int nch = idx >> 14;
    float sy = (float)(Y*63)/255.f;
    int yl=(int)sy; int yh=min(yl+1,63); float fy=sy-yl;
    const float* z0 = g_z + (size_t)nch*4096 + yl*64;
    const float* z1 = g_z + (size_t)nch*4096 + yh*64;
    float4 r;
    float* rp = &r.x;
    #pragma unroll
    for (int k=0;k<4;k++){
        int X_ = xb4 + k;
        float sx = (float)(X_*63)/255.f;
        int xl=(int)sx; int xh=min(xl+1,63); float fx=sx-xl;
        rp[k] = (z0[xl]*(1.f-fx)+z0[xh]*fx)*(1.f-fy)
              + (z1[xl]*(1.f-fx)+z1[xh]*fx)*fy;
    }
    float4 xin = *(const float4*)(x + ((size_t)idx<<2));
    r.x += xin.x; r.y += xin.y; r.z += xin.z; r.w += xin.w;
    *(float4*)(out + ((size_t)idx<<2)) = r;
}

// ---------- host ----------
extern "C" void kernel_launch(void* const* d_in, const int* in_sizes, int n_in,
                              void* d_out, int out_size){
    const float* x       = (const float*)d_in[0];
    const float* depth   = (const float*)d_in[1];
    const float* down_w  = (const float*)d_in[2];
    const float* theta_w = (const float*)d_in[3];
    const float* theta_b = (const float*)d_in[4];
    const float* phi_w   = (const float*)d_in[5];
    const float* phi_b   = (const float*)d_in[6];
    const float* g_w     = (const float*)d_in[7];
    const float* g_b     = (const float*)d_in[8];
    const float* z_w     = (const float*)d_in[9];
    const float* z_b     = (const float*)d_in[10];
    const float* ppg_pw  = (const float*)d_in[11];
    const float* ppg_gam = (const float*)d_in[12];
    const float* ppg_bet = (const float*)d_in[13];
    const float* ppg_ow  = (const float*)d_in[14];
    const float* ppg_ob  = (const float*)d_in[15];
    const float* ppt_pw  = (const float*)d_in[16];
    const float* ppt_gam = (const float*)d_in[17];
    const float* ppt_bet = (const float*)d_in[18];
    const float* ppt_ow  = (const float*)d_in[19];
    const float* ppt_ob  = (const float*)d_in[20];
    const float* ppp_pw  = (const float*)d_in[21];
    const float* ppp_gam = (const float*)d_in[22];
    const float* ppp_bet = (const float*)d_in[23];
    const float* ppp_ow  = (const float*)d_in[24];
    const float* ppp_ob  = (const float*)d_in[25];
    float* out = (float*)d_out;

    k_down<<<(NB*C*HD*HD + 7*8192)/256, 256>>>(x, down_w, theta_w, g_w, phi_w, z_w,
                                               ppg_ow, ppt_ow, ppp_ow);
    k_convs_hmma<<<NB*32, 384>>>(theta_b, g_b, phi_b);
    k_pool_all<<<3*NB*64, 256>>>();
    k_levelconv_all<<<(3*NB*85*16*8 + 255)/256, 256>>>(ppg_pw, ppg_gam, ppg_bet,
                                                       ppt_pw, ppt_gam, ppt_bet,
                                                       ppp_pw, ppp_gam, ppp_bet);
    k_ppfinal_all<<<384, 256>>>(ppg_ob, ppt_ob, ppp_ob);
    k_attn_hmma<<<NB*32, 512>>>(depth, z_b);
    k_epi<<<(NB*C*H0*H0/4 + 255)/256, 256>>>(x, out);
}

// round 16
// speedup vs baseline: 1.0243x; 1.0120x over previous
#include <cuda_runtime.h>
#include <cuda_bf16.h>
#include <cuda_fp16.h>
#include <math.h>
#include <cstdint>

#define NB 4
#define C 128
#define CC 64
#define H0 256
#define HD 64
#define EPS6 1e-6f
#define BN_INV 0.9999950000374997f
#define E1F 2.7182818284590452f

// ---------- helpers ----------
__device__ __forceinline__ uint32_t s2u(const void* p){
    uint32_t a; asm("{ .reg .u64 t; cvta.to.shared.u64 t, %1; cvt.u32.u64 %0, t; }" : "=r"(a) : "l"(p)); return a;
}
__device__ __forceinline__ void ldsm4(uint32_t* r, uint32_t a){
    asm volatile("ldmatrix.sync.aligned.m8n8.x4.shared.b16 {%0,%1,%2,%3}, [%4];"
        : "=r"(r[0]),"=r"(r[1]),"=r"(r[2]),"=r"(r[3]) : "r"(a));
}
__device__ __forceinline__ void ldsm4t(uint32_t* r, uint32_t a){
    asm volatile("ldmatrix.sync.aligned.m8n8.x4.trans.shared.b16 {%0,%1,%2,%3}, [%4];"
        : "=r"(r[0]),"=r"(r[1]),"=r"(r[2]),"=r"(r[3]) : "r"(a));
}
__device__ __forceinline__ void mma16816(float* d, const uint32_t* a, uint32_t b0, uint32_t b1){
    asm volatile("mma.sync.aligned.m16n8k16.row.col.f32.bf16.bf16.f32 "
        "{%0,%1,%2,%3}, {%4,%5,%6,%7}, {%8,%9}, {%0,%1,%2,%3};"
        : "+f"(d[0]),"+f"(d[1]),"+f"(d[2]),"+f"(d[3])
        : "r"(a[0]),"r"(a[1]),"r"(a[2]),"r"(a[3]), "r"(b0),"r"(b1));
}
// exp(x) for x in [0, 1.2]: half-and-square Taylor deg 6, rel err < 6e-6. Pure FMA.
__device__ __forceinline__ float expp(float x){
    float h = 0.5f*x;
    float p = __fmaf_rn(h, 0.0013888889f, 0.0083333333f);
    p = __fmaf_rn(h, p, 0.0416666667f);
    p = __fmaf_rn(h, p, 0.1666666667f);
    p = __fmaf_rn(h, p, 0.5f);
    p = __fmaf_rn(h, p, 1.0f);
    p = __fmaf_rn(h, p, 1.0f);
    return p*p;
}
__device__ __forceinline__ float sum8bf(uint4 v){
    const __nv_bfloat162* h = (const __nv_bfloat162*)&v;
    float s = 0.f;
    #pragma unroll
    for (int i=0;i<4;i++){ float2 f = __bfloat1622float2(h[i]); s += f.x + f.y; }
    return s;
}

// ---------- scratch ----------
__device__ __align__(16) __nv_bfloat16 g_xd_h[NB*C*4096];
__device__ __align__(16) __nv_bfloat16 g_wcat[192*128];
__device__ __align__(16) __nv_bfloat16 g_zw_h[128*64];
__device__ __align__(16) __nv_bfloat16 g_owcat[3*64*128];
__device__ __align__(16) __nv_bfloat16 g_thin [NB*CC*HD*HD];
__device__ __align__(16) __nv_bfloat16 g_g0   [NB*CC*1024];
__device__ __align__(16) __nv_bfloat16 g_phi0 [NB*CC*1024];
__device__ float g_poolT[3*NB*85*64];
__device__ float g_ppc  [3][NB*85*16];
__device__ __align__(16) __nv_bfloat16 g_th_h [NB*4096*64];
__device__ __align__(16) __nv_bfloat16 g_phi_h[NB*1024*64];
__device__ __align__(16) __nv_bfloat16 g_gv_h [NB*1024*64];
__device__ uint32_t g_lg[NB*4096*512];
__device__ float g_z[NB*C*4096];

// ---------- K1: down conv -> bf16, fused weight prep (wide grid) ----------
__global__ void k_down(const float* __restrict__ x, const float* __restrict__ dw,
                       const float* __restrict__ tw, const float* __restrict__ gw,
                       const float* __restrict__ pw, const float* __restrict__ zw,
                       const float* __restrict__ ow0, const float* __restrict__ ow1,
                       const float* __restrict__ ow2){
    int idx = blockIdx.x*256 + threadIdx.x;
    if (idx < NB*C*HD*HD){
        int j = idx & 63, i = (idx>>6) & 63, nc = idx>>12;
        int ch = nc & (C-1);
        const float* xb = x + ((size_t)nc<<16) + i*4*256 + j*4;
        const float* w = dw + ch*16;
        float s = 0.f;
        #pragma unroll
        for (int a=0; a<4; a++){
            float4 v = *(const float4*)(xb + a*256);
            s += v.x*w[a*4+0] + v.y*w[a*4+1] + v.z*w[a*4+2] + v.w*w[a*4+3];
        }
        g_xd_h[idx] = __float2bfloat16(s);
    } else {
        int i = idx - NB*C*HD*HD;
        if (i < 3*8192){
            int m = i >> 13;
            const float* src = (m==0) ? tw : (m==1) ? gw : pw;
            g_wcat[i] = __float2bfloat16(src[i & 8191]);
        } else if (i < 4*8192){
            g_zw_h[i - 3*8192] = __float2bfloat16(zw[i - 3*8192]);
        } else if (i < 7*8192){
            int m = (i - 4*8192) >> 13;
            const float* src = (m==0) ? ow0 : (m==1) ? ow1 : ow2;
            g_owcat[i - 4*8192] = __float2bfloat16(src[(i - 4*8192) & 8191]);
        }
    }
}

// ---------- K2: theta/g/phi convs via HMMA, maxpool fused ----------
__global__ void __launch_bounds__(384) k_convs_hmma(const float* __restrict__ tb_,
                        const float* __restrict__ gb_, const float* __restrict__ pb_){
    __shared__ __nv_bfloat16 sX[2][128][72];
    int tid = threadIdx.x, w = tid>>5, lane = tid&31;
    int n = blockIdx.x >> 5;
    int tb = blockIdx.x & 31;
    int px0 = tb * 128;
    const __nv_bfloat16* xsrc = g_xd_h + (size_t)n*C*4096;

    int r = lane>>2, cq = (lane&3)*2;
    uint32_t aW[8][4];
    {
        const __nv_bfloat16* w0 = g_wcat + (w*16 + r)*128;
        const __nv_bfloat16* w8 = w0 + 8*128;
        #pragma unroll
        for (int kb=0;kb<8;kb++){
            int c0 = kb*16 + cq;
            aW[kb][0] = *(const uint32_t*)&w0[c0];
            aW[kb][1] = *(const uint32_t*)&w8[c0];
            aW[kb][2] = *(const uint32_t*)&w0[c0+8];
            aW[kb][3] = *(const uint32_t*)&w8[c0+8];
        }
    }
    for (int i=tid; i<2048; i+=384){
        int buf = i>>10, rem = i&1023;
        int c = rem>>3, p = (rem&7)*8;
        *(uint4*)&sX[buf][c][p] = *(const uint4*)&xsrc[c*4096 + px0 + buf*64 + p];
    }
    __syncthreads();

    int grow = (lane&7) + ((lane&8)?8:0);
    int gcol = (lane&16)?8:0;
    int brn = w >> 2, o0 = (w&3)*16;
    const float* bias = (brn==0) ? tb_ : (brn==1) ? gb_ : pb_;
    float ba = bias[o0 + r], bb = bias[o0 + r + 8];
    int colb = (lane&3)*2;

    float hm0[2][8], hm8[2][8];
    __nv_bfloat16* row0 = g_thin + ((size_t)n*CC + o0 + r)*4096 + px0;
    __nv_bfloat16* row8 = row0 + 8*4096;

    #pragma unroll
    for (int t=0;t<2;t++){
        float acc[8][4];
        #pragma unroll
        for (int i=0;i<8;i++){ acc[i][0]=0.f;acc[i][1]=0.f;acc[i][2]=0.f;acc[i][3]=0.f; }
        #pragma unroll
        for (int kb=0;kb<8;kb++){
            int kr = kb*16 + grow;
            #pragma unroll
            for (int np=0;np<4;np++){
                uint32_t bg[4];
                ldsm4t(bg, s2u(&sX[t][kr][np*16 + gcol]));
                mma16816(acc[2*np], aW[kb], bg[0], bg[1]);
                mma16816(acc[2*np+1], aW[kb], bg[2], bg[3]);
            }
        }
        if (brn == 0){
            #pragma unroll
            for (int nf=0;nf<8;nf++){
                int px = t*64 + nf*8 + colb;
                __nv_bfloat162 v0 = __floats2bfloat162_rn(acc[nf][0]+ba, acc[nf][1]+ba);
                __nv_bfloat162 v8 = __floats2bfloat162_rn(acc[nf][2]+bb, acc[nf][3]+bb);
                *(uint32_t*)&row0[px] = *(uint32_t*)&v0;
                *(uint32_t*)&row8[px] = *(uint32_t*)&v8;
            }
        } else {
            #pragma unroll
            for (int nf=0;nf<8;nf++){
                hm0[t][nf] = fmaxf(acc[nf][0], acc[nf][1]);
                hm8[t][nf] = fmaxf(acc[nf][2], acc[nf][3]);
            }
        }
    }
    if (brn != 0){
        __nv_bfloat16* dst = ((brn==1) ? g_g0 : g_phi0) + ((size_t)n*CC + o0 + r)*1024 + tb*32;
        int vx = lane&3;
        #pragma unroll
        for (int nf=0;nf<8;nf++){
            dst[nf*4 + vx]          = __float2bfloat16(fmaxf(hm0[0][nf], hm0[1][nf]) + ba);
            dst[8*1024 + nf*4 + vx] = __float2bfloat16(fmaxf(hm8[0][nf], hm8[1][nf]) + bb);
        }
    }
}

// ---------- K3: pyramid pools ----------
__global__ void __launch_bounds__(256) k_pool_all(){
    __shared__ float sp[4][64];
    __shared__ float s8[64], s4[16], s2[4];
    int bid = blockIdx.x;
    int br = bid >> 8; int nc = bid & 255;
    int n = nc >> 6, c = nc & 63;
    int bn = br*NB + n;
    int H = (br==1) ? 64 : 32;
    const __nv_bfloat16* in = (br==0) ? g_g0 : (br==1) ? g_thin : g_phi0;
    const __nv_bfloat16* p = in + (size_t)nc*H*H;
    int t = threadIdx.x & 63, q = threadIdx.x >> 6;
    int k0 = H >> 3;
    int cy = t>>3, cx = t&7;
    const __nv_bfloat16* cell = p + (cy*k0)*H + cx*k0;
    float s = 0.f;
    if (k0 == 8){
        #pragma unroll
        for (int a=0;a<2;a++){
            const uint4* rp = (const uint4*)(cell + (q*2+a)*H);
            s += sum8bf(rp[0]);
        }
    } else {
        const __nv_bfloat162* hp = (const __nv_bfloat162*)(cell + q*H);
        float2 f0 = __bfloat1622float2(hp[0]);
        float2 f1 = __bfloat1622float2(hp[1]);
        s = f0.x+f0.y+f1.x+f1.y;
    }
    sp[q][t] = s;
    __syncthreads();
    float* ob = g_poolT + (size_t)bn*85*64 + c;
    if (threadIdx.x < 64){
        float tot = sp[0][threadIdx.x]+sp[1][threadIdx.x]+sp[2][threadIdx.x]+sp[3][threadIdx.x];
        s8[threadIdx.x] = tot;
        ob[threadIdx.x*64] = tot / (float)(k0*k0);
    }
    __syncthreads();
    if (threadIdx.x < 16){
        int tt = threadIdx.x;
        int yy=tt>>2, xx=tt&3;
        float v = s8[(2*yy)*8+2*xx] + s8[(2*yy)*8+2*xx+1] + s8[(2*yy+1)*8+2*xx] + s8[(2*yy+1)*8+2*xx+1];
        s4[tt]=v; ob[(64+tt)*64] = v / (float)(4*k0*k0);
    }
    __syncthreads();
    if (threadIdx.x < 4){
        int tt = threadIdx.x;
        int yy=tt>>1, xx=tt&1;
        float v = s4[(2*yy)*4+2*xx] + s4[(2*yy)*4+2*xx+1] + s4[(2*yy+1)*4+2*xx] + s4[(2*yy+1)*4+2*xx+1];
        s2[tt]=v; ob[(80+tt)*64] = v / (float)(16*k0*k0);
    }
    __syncthreads();
    if (threadIdx.x == 0) ob[84*64] = (s2[0]+s2[1]+s2[2]+s2[3]) / (float)(64*k0*k0);
}

// ---------- K4: level convs, 8 threads/output ----------
__global__ void k_levelconv_all(const float* __restrict__ pw0, const float* __restrict__ g0, const float* __restrict__ b0,
                                const float* __restrict__ pw1, const float* __restrict__ g1, const float* __restrict__ b1,
                                const float* __restrict__ pw2, const float* __restrict__ g2, const float* __restrict__ b2){
    int gidx = blockIdx.x*blockDim.x + threadIdx.x;
    if (gidx >= 3*NB*85*16*8) return;
    int j = gidx & 7;
    int idx = gidx >> 3;
    int o = idx & 15;
    int s = (idx>>4) % 85;
    int bn = idx / (85*16);
    int br = bn >> 2, nn = bn & 3;
    const float* pw = (br==0)?pw0:(br==1)?pw1:pw2;
    const float* gamma = (br==0)?g0:(br==1)?g1:g2;
    const float* beta = (br==0)?b0:(br==1)?b1:b2;
    int lvl = (s<64) ? 0 : (s<80 ? 1 : (s<84 ? 2 : 3));
    const float4* w4 = (const float4*)(pw + (lvl*16+o)*64) + j*2;
    const float4* p4 = (const float4*)(g_poolT + (size_t)bn*85*64 + s*64) + j*2;
    float acc = 0.f;
    #pragma unroll
    for (int i=0;i<2;i++){
        float4 a = __ldg(&w4[i]);
        float4 b = p4[i];
        acc += a.x*b.x + a.y*b.y + a.z*b.z + a.w*b.w;
    }
    acc += __shfl_xor_sync(~0u, acc, 1);
    acc += __shfl_xor_sync(~0u, acc, 2);
    acc += __shfl_xor_sync(~0u, acc, 4);
    if (j == 0){
        acc = acc*BN_INV*__ldg(&gamma[lvl*16+o]) + __ldg(&beta[lvl*16+o]);
        g_ppc[br][(nn*85+s)*16+o] = fmaxf(acc, 0.f);
    }
}

// ---------- K5: pyramid final convs via HMMA (shift-based indexing) ----------
__global__ void __launch_bounds__(256) k_ppfinal_all(
        const float* __restrict__ ob0, const float* __restrict__ ob1, const float* __restrict__ ob2){
    __shared__ __nv_bfloat16 sB[128][72];
    __shared__ __nv_bfloat16 sO[64][72];
    __shared__ float spp[85*16];
    int bid = blockIdx.x;
    int br, n, t0;
    if (bid < 256){ br = 1; n = bid>>6; t0 = (bid&63)<<6; }
    else {
        int r = bid - 256;
        br = (r < 64) ? 0 : 2;
        int r2 = r & 63;
        n = r2 >> 4; t0 = (r2 & 15) << 6;
    }
    const float* ob = (br==0)?ob0:(br==1)?ob1:ob2;
    int hs = (br==1) ? 6 : 5;
    int H = 1 << hs;
    int P = H*H;
    const __nv_bfloat16* X = (br==0) ? g_g0 : (br==1) ? g_thin : g_phi0;
    const __nv_bfloat16* xin = X + (size_t)n*CC*P;
    int tid = threadIdx.x, w = tid>>5, lane = tid&31;
    for (int i=tid; i<512; i+=256){
        int c = i>>3, p8 = (i&7)*8;
        *(uint4*)&sB[c][p8] = *(const uint4*)&xin[c*P + t0 + p8];
    }
    for (int i=tid; i<1360; i+=256) spp[i] = g_ppc[br][n*1360 + i];
    __syncthreads();
    float invH = 1.0f / (float)H;
    for (int e = tid; e < 4096; e += 256){
        int u = e>>6, p = e&63;
        int lvl = u>>4, j = u&15;
        int pix = t0 + p; int y = pix >> hs, x = pix & (H-1);
        int ps = 8 >> lvl;
        int off = (lvl==0) ? 0 : (lvl==1 ? 64 : (lvl==2 ? 80 : 84));
        float sy = fminf(fmaxf((y+0.5f)*ps*invH - 0.5f, 0.f), (float)(ps-1));
        float sx = fminf(fmaxf((x+0.5f)*ps*invH - 0.5f, 0.f), (float)(ps-1));
        int yl=(int)sy; int yh=min(yl+1, ps-1); float fy=sy-yl;
        int xl=(int)sx; int xh=min(xl+1, ps-1); float fx=sx-xl;
        const float* b00 = spp + (off + yl*ps + xl)*16;
        const float* b01 = spp + (off + yl*ps + xh)*16;
        const float* b10 = spp + (off + yh*ps + xl)*16;
        const float* b11 = spp + (off + yh*ps + xh)*16;
        float v = (b00[j]*(1.f-fx)+b01[j]*fx)*(1.f-fy) + (b10[j]*(1.f-fx)+b11[j]*fx)*fy;
        sB[64+u][p] = __float2bfloat16(v);
    }
    __syncthreads();
    int mt = w & 3, ph = w >> 2;
    int ra = lane>>2, colb = (lane&3)*2, cq = (lane&3)*2;
    uint32_t aW[8][4];
    {
        const __nv_bfloat16* w0 = g_owcat + br*8192 + (mt*16 + ra)*128;
        const __nv_bfloat16* w8 = w0 + 8*128;
        #pragma unroll
        for (int kb=0;kb<8;kb++){
            int c0 = kb*16 + cq;
            aW[kb][0] = *(const uint32_t*)&w0[c0];
            aW[kb][1] = *(const uint32_t*)&w8[c0];
            aW[kb][2] = *(const uint32_t*)&w0[c0+8];
            aW[kb][3] = *(const uint32_t*)&w8[c0+8];
        }
    }
    int grow = (lane&7) + ((lane&8)?8:0);
    int gcol = (lane&16)?8:0;
    float acc[4][4];
    #pragma unroll
    for (int i=0;i<4;i++){ acc[i][0]=0.f;acc[i][1]=0.f;acc[i][2]=0.f;acc[i][3]=0.f; }
    #pragma unroll
    for (int kb=0;kb<8;kb++){
        int kr = kb*16 + grow;
        #pragma unroll
        for (int np=0;np<2;np++){
            uint32_t bg[4];
            ldsm4t(bg, s2u(&sB[kr][ph*32 + np*16 + gcol]));
            mma16816(acc[2*np], aW[kb], bg[0], bg[1]);
            mma16816(acc[2*np+1], aW[kb], bg[2], bg[3]);
        }
    }
    float ba = ob[mt*16 + ra], bb = ob[mt*16 + ra + 8];
    #pragma unroll
    for (int nf=0;nf<4;nf++){
        int px = ph*32 + (nf>>1)*16 + (nf&1)*8 + colb;
        sO[px][mt*16+ra]     = __float2bfloat16(acc[nf][0]+ba);
        sO[px+1][mt*16+ra]   = __float2bfloat16(acc[nf][1]+ba);
        sO[px][mt*16+ra+8]   = __float2bfloat16(acc[nf][2]+bb);
        sO[px+1][mt*16+ra+8] = __float2bfloat16(acc[nf][3]+bb);
    }
    __syncthreads();
    __nv_bfloat16* dst = (br==1) ? (g_th_h + ((size_t)n*4096 + t0)*64)
                      : (br==0) ? (g_gv_h + ((size_t)n*1024 + t0)*64)
                                : (g_phi_h + ((size_t)n*1024 + t0)*64);
    for (int i=tid; i<512; i+=256){
        int px = i>>3, o8 = (i&7)*8;
        *(uint4*)&dst[px*64 + o8] = *(const uint4*)&sO[px][o8];
    }
}

// ---------- bilinear on 256x256 ----------
__device__ __forceinline__ float bil256(const float* p, float sy, float sx){
    int yl=(int)sy; int yh=min(yl+1,255); float fy=sy-yl;
    int xl=(int)sx; int xh=min(xl+1,255); float fx=sx-xl;
    return (p[yl*256+xl]*(1.f-fx)+p[yl*256+xh]*fx)*(1.f-fy)
         + (p[yh*256+xl]*(1.f-fx)+p[yh*256+xh]*fx)*fy;
}

// ---------- K6: HMMA attention + fused z-conv epilogue ----------
__global__ void __launch_bounds__(512,1) k_attn_hmma(const float* __restrict__ depth,
                                                     const float* __restrict__ zb){
    __shared__ __align__(16) char RAW[36864];
    __shared__ float2 d2s[1024];
    __shared__ float d1s[128];
    __shared__ float ss3[2][128];
    __nv_bfloat16* sA = (__nv_bfloat16*)RAW;
    __nv_bfloat16* sB = (__nv_bfloat16*)(RAW + 18432);
    float* STF = (float*)RAW;
    int tid = threadIdx.x, w = tid>>5, lane = tid&31;
    int qt = w & 7, nh = w >> 3;
    int n = blockIdx.x>>5, q0 = (blockIdx.x&31)*128;

    const float* dm = depth + (size_t)n*65536;
    for (int i=tid;i<1024;i+=512){
        int yy=i>>5, xx=i&31;
        float d2 = bil256(dm, (float)(yy*255)/31.f, (float)(xx*255)/31.f);
        d2s[i] = make_float2(d2, __fdividef(1.f, d2+EPS6));
    }
    if (tid < 128){
        int q = q0 + tid;
        d1s[tid] = bil256(dm, (float)((q>>6)*255)/63.f, (float)((q&63)*255)/63.f);
    }
    const uint4* qg = (const uint4*)(g_th_h + ((size_t)(n*4096+q0))*64);
    for (int i=tid;i<1024;i+=512)
        *(uint4*)&sA[(i>>3)*72 + (i&7)*8] = qg[i];
    __syncthreads();
    uint32_t sAu = s2u(sA), sBu = s2u(sB);
    uint32_t aQ[4][4];
    {
        int arow = qt*16 + (lane&15);
        int acol = (lane>>4)<<3;
        #pragma unroll
        for (int kb=0;kb<4;kb++)
            ldsm4(aQ[kb], sAu + (uint32_t)((arow*72 + kb*16 + acol)*2));
    }
    int ra = lane>>2, colb = (lane&3)*2;
    int r0_ = qt*16 + ra, r1_ = r0_ + 8;
    float d1a = d1s[r0_], d1b = d1s[r1_];
    float ir1a = __fdividef(1.f,d1a+EPS6), ir1b = __fdividef(1.f,d1b+EPS6);
    __syncthreads();

    int brow = (lane&7) + ((lane&16)?8:0);
    int bcol = (lane&8)?8:0;
    int grow = (lane&7) + ((lane&8)?8:0);
    int gcol = (lane&16)?8:0;
    const uint4* phg = (const uint4*)(g_phi_h + (size_t)n*65536);
    const uint4* gg  = (const uint4*)(g_gv_h + (size_t)n*65536);
    uint32_t* lg = g_lg + ((size_t)(n*4096 + q0))*512;
    int lrowa = r0_*512, lrowb = r1_*512;

    float s1a=0.f, s2a=0.f, s1b=0.f, s2b=0.f;

    for (int i=tid;i<1024;i+=512)
        *(uint4*)&sA[(i>>3)*72+(i&7)*8] = phg[i];
    __syncthreads();

    // ===== pass 1: w = exp(l)*exp(r-1)*e (MUFU dedup) =====
    for (int t=0;t<8;t++){
        uint32_t curu = (t&1) ? sBu : sAu;
        __nv_bfloat16* nxt = (t&1) ? sA : sB;
        uint4 pre0, pre1;
        if (t<7){ pre0 = phg[(t+1)*1024 + tid]; pre1 = phg[(t+1)*1024 + tid + 512]; }
        float L[8][4];
        #pragma unroll
        for (int nt=0;nt<8;nt++){ L[nt][0]=0.f;L[nt][1]=0.f;L[nt][2]=0.f;L[nt][3]=0.f; }
        #pragma unroll
        for (int kb=0;kb<4;kb++){
            #pragma unroll
            for (int ng=0;ng<4;ng++){
                uint32_t bq[4];
                int br_ = nh*64 + ng*16 + brow;
                ldsm4(bq, curu + (uint32_t)((br_*72 + kb*16 + bcol)*2));
                mma16816(L[2*ng], aQ[kb], bq[0], bq[1]);
                mma16816(L[2*ng+1], aQ[kb], bq[2], bq[3]);
            }
        }
        if (t<7){
            int i0 = tid;       *(uint4*)&nxt[(i0>>3)*72+(i0&7)*8] = pre0;
            i0 = tid + 512;     *(uint4*)&nxt[(i0>>3)*72+(i0&7)*8] = pre1;
        }
        int cwb = t*64 + nh*32 + (lane&3);
        #pragma unroll
        for (int nt=0;nt<8;nt++){
            int v = t*128 + nh*64 + nt*8 + colb;
            float2 dp = d2s[v], dq = d2s[v+1];
            float r0 = fminf(d1a*dp.y, dp.x*ir1a);
            float r1 = fminf(d1a*dq.y, dq.x*ir1a);
            float r2 = fminf(d1b*dp.y, dp.x*ir1b);
            float r3 = fminf(d1b*dq.y, dq.x*ir1b);
            float p0 = __expf(r0-1.f), p1 = __expf(r1-1.f);
            float p2 = __expf(r2-1.f), p3 = __expf(r3-1.f);
            s2a += p0+p1; s2b += p2+p3;
            float el0 = __expf(L[nt][0]), el1 = __expf(L[nt][1]);
            float el2 = __expf(L[nt][2]), el3 = __expf(L[nt][3]);
            s1a += el0+el1; s1b += el2+el3;
            __half2 ha = __floats2half2_rn(el0*p0*E1F, el1*p1*E1F);
            __half2 hb = __floats2half2_rn(el2*p2*E1F, el3*p3*E1F);
            lg[lrowa + cwb + nt*4] = *(uint32_t*)&ha;
            lg[lrowb + cwb + nt*4] = *(uint32_t*)&hb;
        }
        __syncthreads();
    }

    #pragma unroll
    for (int o=1;o<=2;o<<=1){
        s1a += __shfl_xor_sync(~0u,s1a,o);
        s1b += __shfl_xor_sync(~0u,s1b,o);
        s2a += __shfl_xor_sync(~0u,s2a,o);
        s2b += __shfl_xor_sync(~0u,s2b,o);
    }
    if ((lane&3)==0){
        STF[      nh*128 + r0_] = s1a;  STF[      nh*128 + r1_] = s1b;
        STF[256 + nh*128 + r0_] = s2a;  STF[256 + nh*128 + r1_] = s2b;
    }
    __syncthreads();
    float S1a = STF[r0_] + STF[128+r0_];
    float S2a = (STF[256+r0_] + STF[256+128+r0_]) * E1F;
    float S1b = STF[r1_] + STF[128+r1_];
    float S2b = (STF[256+r1_] + STF[256+128+r1_]) * E1F;
    float c1a = __fdividef(1.f, S1a*S2a);
    float c1b = __fdividef(1.f, S1b*S2b);
    __syncthreads();

    // ===== pass 2 =====
    float Y[8][4];
    #pragma unroll
    for (int i=0;i<8;i++){ Y[i][0]=0.f;Y[i][1]=0.f;Y[i][2]=0.f;Y[i][3]=0.f; }
    float s3a=0.f, s3b=0.f;
    for (int i=tid;i<1024;i+=512)
        *(uint4*)&sA[(i>>3)*72+(i&7)*8] = gg[i];
    __syncthreads();
    for (int t=0;t<8;t++){
        uint32_t curu = (t&1) ? sBu : sAu;
        __nv_bfloat16* nxt = (t&1) ? sA : sB;
        uint4 pre0, pre1;
        if (t<7){ pre0 = gg[(t+1)*1024 + tid]; pre1 = gg[(t+1)*1024 + tid + 512]; }
        int cwb = t*64 + nh*32 + (lane&3);
        uint32_t lwa[8], lwb[8];
        #pragma unroll
        for (int nt=0;nt<8;nt++){
            lwa[nt] = lg[lrowa + cwb + nt*4];
            lwb[nt] = lg[lrowb + cwb + nt*4];
        }
        uint32_t ek[4][4];
        #pragma unroll
        for (int nt=0;nt<8;nt++){
            float2 la = __half22float2(*(__half2*)&lwa[nt]);
            float2 lb = __half22float2(*(__half2*)&lwb[nt]);
            float e0 = expp(c1a*la.x);
            float e1 = expp(c1a*la.y);
            float e2 = expp(c1b*lb.x);
            float e3 = expp(c1b*lb.y);
            s3a += e0+e1; s3b += e2+e3;
            __nv_bfloat162 pa2 = __floats2bfloat162_rn(e0,e1);
            __nv_bfloat162 pb2 = __floats2bfloat162_rn(e2,e3);
            int kb = nt>>1, hh = (nt&1)<<1;
            ek[kb][hh]   = *(uint32_t*)&pa2;
            ek[kb][hh+1] = *(uint32_t*)&pb2;
        }
        #pragma unroll
        for (int kb=0;kb<4;kb++){
            #pragma unroll
            for (int np=0;np<4;np++){
                uint32_t bg[4];
                int gr = nh*64 + kb*16 + grow;
                ldsm4t(bg, curu + (uint32_t)((gr*72 + np*16 + gcol)*2));
                mma16816(Y[2*np], ek[kb], bg[0], bg[1]);
                mma16816(Y[2*np+1], ek[kb], bg[2], bg[3]);
            }
        }
        if (t<7){
            int i0 = tid;       *(uint4*)&nxt[(i0>>3)*72+(i0&7)*8] = pre0;
            i0 = tid + 512;     *(uint4*)&nxt[(i0>>3)*72+(i0&7)*8] = pre1;
        }
        __syncthreads();
    }
    s3a += __shfl_xor_sync(~0u,s3a,1); s3a += __shfl_xor_sync(~0u,s3a,2);
    s3b += __shfl_xor_sync(~0u,s3b,1); s3b += __shfl_xor_sync(~0u,s3b,2);
    if ((lane&3)==0){ ss3[nh][r0_] = s3a; ss3[nh][r1_] = s3b; }
    __nv_bfloat16 (*ysh)[68] = (__nv_bfloat16(*)[68])RAW;
    __nv_bfloat16 (*sYf)[72] = (__nv_bfloat16(*)[72])(RAW + 18432);
    __syncthreads();
    if (nh == 0){
        #pragma unroll
        for (int np2=0;np2<8;np2++){
            int c_ = np2*8 + colb;
            ysh[r0_][c_]   = __float2bfloat16(Y[np2][0]);
            ysh[r0_][c_+1] = __float2bfloat16(Y[np2][1]);
            ysh[r1_][c_]   = __float2bfloat16(Y[np2][2]);
            ysh[r1_][c_+1] = __float2bfloat16(Y[np2][3]);
        }
    }
    __syncthreads();
    if (nh == 1){
        float i3a = __fdividef(1.f, ss3[0][r0_] + ss3[1][r0_]);
        float i3b = __fdividef(1.f, ss3[0][r1_] + ss3[1][r1_]);
        #pragma unroll
        for (int np2=0;np2<8;np2++){
            int c_ = np2*8 + colb;
            __nv_bfloat162 va = __floats2bfloat162_rn(
                (Y[np2][0]+__bfloat162float(ysh[r0_][c_]))*i3a,
                (Y[np2][1]+__bfloat162float(ysh[r0_][c_+1]))*i3a);
            __nv_bfloat162 vb = __floats2bfloat162_rn(
                (Y[np2][2]+__bfloat162float(ysh[r1_][c_]))*i3b,
                (Y[np2][3]+__bfloat162float(ysh[r1_][c_+1]))*i3b);
            *(uint32_t*)&sYf[r0_][c_] = *(uint32_t*)&va;
            *(uint32_t*)&sYf[r1_][c_] = *(uint32_t*)&vb;
        }
    }
    __syncthreads();
    // fused z conv
    {
        uint32_t aWz[4][4];
        const __nv_bfloat16* w0 = g_zw_h + (qt*16 + ra)*64;
        const __nv_bfloat16* w8 = w0 + 8*64;
        #pragma unroll
        for (int kb=0;kb<4;kb++){
            int c0 = kb*16 + colb;
            aWz[kb][0] = *(const uint32_t*)&w0[c0];
            aWz[kb][1] = *(const uint32_t*)&w8[c0];
            aWz[kb][2] = *(const uint32_t*)&w0[c0+8];
            aWz[kb][3] = *(const uint32_t*)&w8[c0+8];
        }
        float accz[8][4];
        #pragma unroll
        for (int i=0;i<8;i++){ accz[i][0]=0.f;accz[i][1]=0.f;accz[i][2]=0.f;accz[i][3]=0.f; }
        #pragma unroll
        for (int kb=0;kb<4;kb++){
            #pragma unroll
            for (int ng=0;ng<4;ng++){
                uint32_t bq[4];
                ldsm4(bq, s2u(&sYf[nh*64 + ng*16 + brow][kb*16 + bcol]));
                mma16816(accz[2*ng], aWz[kb], bq[0], bq[1]);
                mma16816(accz[2*ng+1], aWz[kb], bq[2], bq[3]);
            }
        }
        float ba = zb[qt*16 + ra], bb = zb[qt*16 + ra + 8];
        float* zr0 = g_z + ((size_t)n*C + qt*16 + ra)*4096 + q0 + nh*64;
        float* zr8 = zr0 + 8*4096;
        #pragma unroll
        for (int ng=0;ng<4;ng++){
            #pragma unroll
            for (int j=0;j<2;j++){
                int px = ng*16 + j*8 + colb;
                *(float2*)&zr0[px] = make_float2(accz[2*ng+j][0]+ba, accz[2*ng+j][1]+ba);
                *(float2*)&zr8[px] = make_float2(accz[2*ng+j][2]+bb, accz[2*ng+j][3]+bb);
            }
        }
    }
}

// ---------- K7: epilogue ----------
__global__ void k_epi(const float* __restrict__ x, float* __restrict__ out){
    int idx = blockIdx.x*blockDim.x + threadIdx.x;
    if (idx >= NB*C*H0*H0/4) return;
    int xb4 = (idx & 63) << 2;
    int Y = (idx>>6) & 255;
    int nch = idx >> 14;
    float sy = (float)(Y*63)/255.f;
    int yl=(int)sy; int yh=min(yl+1,63); float fy=sy-yl;
    const float* z0 = g_z + (size_t)nch*4096 + yl*64;
    const float* z1 = g_z + (size_t)nch*4096 + yh*64;
    float4 r;
    float* rp = &r.x;
    #pragma unroll
    for (int k=0;k<4;k++){
        int X_ = xb4 + k;
        float sx = (float)(X_*63)/255.f;
        int xl=(int)sx; int xh=min(xl+1,63); float fx=sx-xl;
        rp[k] = (z0[xl]*(1.f-fx)+z0[xh]*fx)*(1.f-fy)
              + (z1[xl]*(1.f-fx)+z1[xh]*fx)*fy;
    }
    float4 xin = *(const float4*)(x + ((size_t)idx<<2));
    r.x += xin.x; r.y += xin.y; r.z += xin.z; r.w += xin.w;
    *(float4*)(out + ((size_t)idx<<2)) = r;
}

// ---------- host ----------
extern "C" void kernel_launch(void* const* d_in, const int* in_sizes, int n_in,
                              void* d_out, int out_size){
    const float* x       = (const float*)d_in[0];
    const float* depth   = (const float*)d_in[1];
    const float* down_w  = (const float*)d_in[2];
    const float* theta_w = (const float*)d_in[3];
    const float* theta_b = (const float*)d_in[4];
    const float* phi_w   = (const float*)d_in[5];
    const float* phi_b   = (const float*)d_in[6];
    const float* g_w     = (const float*)d_in[7];
    const float* g_b     = (const float*)d_in[8];
    const float* z_w     = (const float*)d_in[9];
    const float* z_b     = (const float*)d_in[10];
    const float* ppg_pw  = (const float*)d_in[11];
    const float* ppg_gam = (const float*)d_in[12];
    const float* ppg_bet = (const float*)d_in[13];
    const float* ppg_ow  = (const float*)d_in[14];
    const float* ppg_ob  = (const float*)d_in[15];
    const float* ppt_pw  = (const float*)d_in[16];
    const float* ppt_gam = (const float*)d_in[17];
    const float* ppt_bet = (const float*)d_in[18];
    const float* ppt_ow  = (const float*)d_in[19];
    const float* ppt_ob  = (const float*)d_in[20];
    const float* ppp_pw  = (const float*)d_in[21];
    const float* ppp_gam = (const float*)d_in[22];
    const float* ppp_bet = (const float*)d_in[23];
    const float* ppp_ow  = (const float*)d_in[24];
    const float* ppp_ob  = (const float*)d_in[25];
    float* out = (float*)d_out;

    k_down<<<(NB*C*HD*HD + 7*8192)/256, 256>>>(x, down_w, theta_w, g_w, phi_w, z_w,
                                               ppg_ow, ppt_ow, ppp_ow);
    k_convs_hmma<<<NB*32, 384>>>(theta_b, g_b, phi_b);
    k_pool_all<<<3*NB*64, 256>>>();
    k_levelconv_all<<<(3*NB*85*16*8 + 255)/256, 256>>>(ppg_pw, ppg_gam, ppg_bet,
                                                       ppt_pw, ppt_gam, ppt_bet,
                                                       ppp_pw, ppp_gam, ppp_bet);
    k_ppfinal_all<<<384, 256>>>(ppg_ob, ppt_ob, ppp_ob);
    k_attn_hmma<<<NB*32, 512>>>(depth, z_b);
    k_epi<<<(NB*C*H0*H0/4 + 255)/256, 256>>>(x, out);
}

// round 17
// speedup vs baseline: 1.0367x; 1.0121x over previous
#include <cuda_runtime.h>
#include <cuda_bf16.h>
#include <cuda_fp16.h>
#include <math.h>
#include <cstdint>

#define NB 4
#define C 128
#define CC 64
#define H0 256
#define HD 64
#define EPS6 1e-6f
#define BN_INV 0.9999950000374997f
#define E1F 2.7182818284590452f

// ---------- helpers ----------
__device__ __forceinline__ uint32_t s2u(const void* p){
    uint32_t a; asm("{ .reg .u64 t; cvta.to.shared.u64 t, %1; cvt.u32.u64 %0, t; }" : "=r"(a) : "l"(p)); return a;
}
__device__ __forceinline__ void ldsm4(uint32_t* r, uint32_t a){
    asm volatile("ldmatrix.sync.aligned.m8n8.x4.shared.b16 {%0,%1,%2,%3}, [%4];"
        : "=r"(r[0]),"=r"(r[1]),"=r"(r[2]),"=r"(r[3]) : "r"(a));
}
__device__ __forceinline__ void ldsm4t(uint32_t* r, uint32_t a){
    asm volatile("ldmatrix.sync.aligned.m8n8.x4.trans.shared.b16 {%0,%1,%2,%3}, [%4];"
        : "=r"(r[0]),"=r"(r[1]),"=r"(r[2]),"=r"(r[3]) : "r"(a));
}
__device__ __forceinline__ void mma16816(float* d, const uint32_t* a, uint32_t b0, uint32_t b1){
    asm volatile("mma.sync.aligned.m16n8k16.row.col.f32.bf16.bf16.f32 "
        "{%0,%1,%2,%3}, {%4,%5,%6,%7}, {%8,%9}, {%0,%1,%2,%3};"
        : "+f"(d[0]),"+f"(d[1]),"+f"(d[2]),"+f"(d[3])
        : "r"(a[0]),"r"(a[1]),"r"(a[2]),"r"(a[3]), "r"(b0),"r"(b1));
}
// exp(x) for x in [0, 1.2]: half-and-square Taylor deg 6, rel err < 6e-6. Pure FMA.
__device__ __forceinline__ float expp(float x){
    float h = 0.5f*x;
    float p = __fmaf_rn(h, 0.0013888889f, 0.0083333333f);
    p = __fmaf_rn(h, p, 0.0416666667f);
    p = __fmaf_rn(h, p, 0.1666666667f);
    p = __fmaf_rn(h, p, 0.5f);
    p = __fmaf_rn(h, p, 1.0f);
    p = __fmaf_rn(h, p, 1.0f);
    return p*p;
}
__device__ __forceinline__ float sum8bf(uint4 v){
    const __nv_bfloat162* h = (const __nv_bfloat162*)&v;
    float s = 0.f;
    #pragma unroll
    for (int i=0;i<4;i++){ float2 f = __bfloat1622float2(h[i]); s += f.x + f.y; }
    return s;
}

// ---------- scratch ----------
__device__ __align__(16) __nv_bfloat16 g_xd_h[NB*C*4096];
__device__ __align__(16) __nv_bfloat16 g_wcat[192*128];
__device__ __align__(16) __nv_bfloat16 g_zw_h[128*64];
__device__ __align__(16) __nv_bfloat16 g_owcat[3*64*128];
__device__ __align__(16) __nv_bfloat16 g_thin [NB*CC*HD*HD];
__device__ __align__(16) __nv_bfloat16 g_g0   [NB*CC*1024];
__device__ __align__(16) __nv_bfloat16 g_phi0 [NB*CC*1024];
__device__ float g_poolT[3*NB*85*64];
__device__ float g_ppc  [3][NB*85*16];
__device__ __align__(16) __nv_bfloat16 g_th_h [NB*4096*64];
__device__ __align__(16) __nv_bfloat16 g_phi_h[NB*1024*64];
__device__ __align__(16) __nv_bfloat16 g_gv_h [NB*1024*64];
__device__ uint32_t g_lg[NB*4096*512];
__device__ float g_z[NB*C*4096];

// ---------- K1: down conv -> bf16, fused weight prep (wide grid) ----------
__global__ void k_down(const float* __restrict__ x, const float* __restrict__ dw,
                       const float* __restrict__ tw, const float* __restrict__ gw,
                       const float* __restrict__ pw, const float* __restrict__ zw,
                       const float* __restrict__ ow0, const float* __restrict__ ow1,
                       const float* __restrict__ ow2){
    int idx = blockIdx.x*256 + threadIdx.x;
    if (idx < NB*C*HD*HD){
        int j = idx & 63, i = (idx>>6) & 63, nc = idx>>12;
        int ch = nc & (C-1);
        const float* xb = x + ((size_t)nc<<16) + i*4*256 + j*4;
        const float* w = dw + ch*16;
        float s = 0.f;
        #pragma unroll
        for (int a=0; a<4; a++){
            float4 v = *(const float4*)(xb + a*256);
            s += v.x*w[a*4+0] + v.y*w[a*4+1] + v.z*w[a*4+2] + v.w*w[a*4+3];
        }
        g_xd_h[idx] = __float2bfloat16(s);
    } else {
        int i = idx - NB*C*HD*HD;
        if (i < 3*8192){
            int m = i >> 13;
            const float* src = (m==0) ? tw : (m==1) ? gw : pw;
            g_wcat[i] = __float2bfloat16(src[i & 8191]);
        } else if (i < 4*8192){
            g_zw_h[i - 3*8192] = __float2bfloat16(zw[i - 3*8192]);
        } else if (i < 7*8192){
            int m = (i - 4*8192) >> 13;
            const float* src = (m==0) ? ow0 : (m==1) ? ow1 : ow2;
            g_owcat[i - 4*8192] = __float2bfloat16(src[(i - 4*8192) & 8191]);
        }
    }
}

// ---------- K2: theta/g/phi convs via HMMA, maxpool fused ----------
__global__ void __launch_bounds__(384) k_convs_hmma(const float* __restrict__ tb_,
                        const float* __restrict__ gb_, const float* __restrict__ pb_){
    __shared__ __nv_bfloat16 sX[2][128][72];
    int tid = threadIdx.x, w = tid>>5, lane = tid&31;
    int n = blockIdx.x >> 5;
    int tb = blockIdx.x & 31;
    int px0 = tb * 128;
    const __nv_bfloat16* xsrc = g_xd_h + (size_t)n*C*4096;

    int r = lane>>2, cq = (lane&3)*2;
    uint32_t aW[8][4];
    {
        const __nv_bfloat16* w0 = g_wcat + (w*16 + r)*128;
        const __nv_bfloat16* w8 = w0 + 8*128;
        #pragma unroll
        for (int kb=0;kb<8;kb++){
            int c0 = kb*16 + cq;
            aW[kb][0] = *(const uint32_t*)&w0[c0];
            aW[kb][1] = *(const uint32_t*)&w8[c0];
            aW[kb][2] = *(const uint32_t*)&w0[c0+8];
            aW[kb][3] = *(const uint32_t*)&w8[c0+8];
        }
    }
    for (int i=tid; i<2048; i+=384){
        int buf = i>>10, rem = i&1023;
        int c = rem>>3, p = (rem&7)*8;
        *(uint4*)&sX[buf][c][p] = *(const uint4*)&xsrc[c*4096 + px0 + buf*64 + p];
    }
    __syncthreads();

    int grow = (lane&7) + ((lane&8)?8:0);
    int gcol = (lane&16)?8:0;
    int brn = w >> 2, o0 = (w&3)*16;
    const float* bias = (brn==0) ? tb_ : (brn==1) ? gb_ : pb_;
    float ba = bias[o0 + r], bb = bias[o0 + r + 8];
    int colb = (lane&3)*2;

    float hm0[2][8], hm8[2][8];
    __nv_bfloat16* row0 = g_thin + ((size_t)n*CC + o0 + r)*4096 + px0;
    __nv_bfloat16* row8 = row0 + 8*4096;

    #pragma unroll
    for (int t=0;t<2;t++){
        float acc[8][4];
        #pragma unroll
        for (int i=0;i<8;i++){ acc[i][0]=0.f;acc[i][1]=0.f;acc[i][2]=0.f;acc[i][3]=0.f; }
        #pragma unroll
        for (int kb=0;kb<8;kb++){
            int kr = kb*16 + grow;
            #pragma unroll
            for (int np=0;np<4;np++){
                uint32_t bg[4];
                ldsm4t(bg, s2u(&sX[t][kr][np*16 + gcol]));
                mma16816(acc[2*np], aW[kb], bg[0], bg[1]);
                mma16816(acc[2*np+1], aW[kb], bg[2], bg[3]);
            }
        }
        if (brn == 0){
            #pragma unroll
            for (int nf=0;nf<8;nf++){
                int px = t*64 + nf*8 + colb;
                __nv_bfloat162 v0 = __floats2bfloat162_rn(acc[nf][0]+ba, acc[nf][1]+ba);
                __nv_bfloat162 v8 = __floats2bfloat162_rn(acc[nf][2]+bb, acc[nf][3]+bb);
                *(uint32_t*)&row0[px] = *(uint32_t*)&v0;
                *(uint32_t*)&row8[px] = *(uint32_t*)&v8;
            }
        } else {
            #pragma unroll
            for (int nf=0;nf<8;nf++){
                hm0[t][nf] = fmaxf(acc[nf][0], acc[nf][1]);
                hm8[t][nf] = fmaxf(acc[nf][2], acc[nf][3]);
            }
        }
    }
    if (brn != 0){
        __nv_bfloat16* dst = ((brn==1) ? g_g0 : g_phi0) + ((size_t)n*CC + o0 + r)*1024 + tb*32;
        int vx = lane&3;
        #pragma unroll
        for (int nf=0;nf<8;nf++){
            dst[nf*4 + vx]          = __float2bfloat16(fmaxf(hm0[0][nf], hm0[1][nf]) + ba);
            dst[8*1024 + nf*4 + vx] = __float2bfloat16(fmaxf(hm8[0][nf], hm8[1][nf]) + bb);
        }
    }
}

// ---------- K3: pyramid pools ----------
__global__ void __launch_bounds__(256) k_pool_all(){
    __shared__ float sp[4][64];
    __shared__ float s8[64], s4[16], s2[4];
    int bid = blockIdx.x;
    int br = bid >> 8; int nc = bid & 255;
    int n = nc >> 6, c = nc & 63;
    int bn = br*NB + n;
    int H = (br==1) ? 64 : 32;
    const __nv_bfloat16* in = (br==0) ? g_g0 : (br==1) ? g_thin : g_phi0;
    const __nv_bfloat16* p = in + (size_t)nc*H*H;
    int t = threadIdx.x & 63, q = threadIdx.x >> 6;
    int k0 = H >> 3;
    int cy = t>>3, cx = t&7;
    const __nv_bfloat16* cell = p + (cy*k0)*H + cx*k0;
    float s = 0.f;
    if (k0 == 8){
        #pragma unroll
        for (int a=0;a<2;a++){
            const uint4* rp = (const uint4*)(cell + (q*2+a)*H);
            s += sum8bf(rp[0]);
        }
    } else {
        const __nv_bfloat162* hp = (const __nv_bfloat162*)(cell + q*H);
        float2 f0 = __bfloat1622float2(hp[0]);
        float2 f1 = __bfloat1622float2(hp[1]);
        s = f0.x+f0.y+f1.x+f1.y;
    }
    sp[q][t] = s;
    __syncthreads();
    float* ob = g_poolT + (size_t)bn*85*64 + c;
    if (threadIdx.x < 64){
        float tot = sp[0][threadIdx.x]+sp[1][threadIdx.x]+sp[2][threadIdx.x]+sp[3][threadIdx.x];
        s8[threadIdx.x] = tot;
        ob[threadIdx.x*64] = tot / (float)(k0*k0);
    }
    __syncthreads();
    if (threadIdx.x < 16){
        int tt = threadIdx.x;
        int yy=tt>>2, xx=tt&3;
        float v = s8[(2*yy)*8+2*xx] + s8[(2*yy)*8+2*xx+1] + s8[(2*yy+1)*8+2*xx] + s8[(2*yy+1)*8+2*xx+1];
        s4[tt]=v; ob[(64+tt)*64] = v / (float)(4*k0*k0);
    }
    __syncthreads();
    if (threadIdx.x < 4){
        int tt = threadIdx.x;
        int yy=tt>>1, xx=tt&1;
        float v = s4[(2*yy)*4+2*xx] + s4[(2*yy)*4+2*xx+1] + s4[(2*yy+1)*4+2*xx] + s4[(2*yy+1)*4+2*xx+1];
        s2[tt]=v; ob[(80+tt)*64] = v / (float)(16*k0*k0);
    }
    __syncthreads();
    if (threadIdx.x == 0) ob[84*64] = (s2[0]+s2[1]+s2[2]+s2[3]) / (float)(64*k0*k0);
}

// ---------- K4: level convs, 8 threads/output ----------
__global__ void k_levelconv_all(const float* __restrict__ pw0, const float* __restrict__ g0, const float* __restrict__ b0,
                                const float* __restrict__ pw1, const float* __restrict__ g1, const float* __restrict__ b1,
                                const float* __restrict__ pw2, const float* __restrict__ g2, const float* __restrict__ b2){
    int gidx = blockIdx.x*blockDim.x + threadIdx.x;
    if (gidx >= 3*NB*85*16*8) return;
    int j = gidx & 7;
    int idx = gidx >> 3;
    int o = idx & 15;
    int s = (idx>>4) % 85;
    int bn = idx / (85*16);
    int br = bn >> 2, nn = bn & 3;
    const float* pw = (br==0)?pw0:(br==1)?pw1:pw2;
    const float* gamma = (br==0)?g0:(br==1)?g1:g2;
    const float* beta = (br==0)?b0:(br==1)?b1:b2;
    int lvl = (s<64) ? 0 : (s<80 ? 1 : (s<84 ? 2 : 3));
    const float4* w4 = (const float4*)(pw + (lvl*16+o)*64) + j*2;
    const float4* p4 = (const float4*)(g_poolT + (size_t)bn*85*64 + s*64) + j*2;
    float acc = 0.f;
    #pragma unroll
    for (int i=0;i<2;i++){
        float4 a = __ldg(&w4[i]);
        float4 b = p4[i];
        acc += a.x*b.x + a.y*b.y + a.z*b.z + a.w*b.w;
    }
    acc += __shfl_xor_sync(~0u, acc, 1);
    acc += __shfl_xor_sync(~0u, acc, 2);
    acc += __shfl_xor_sync(~0u, acc, 4);
    if (j == 0){
        acc = acc*BN_INV*__ldg(&gamma[lvl*16+o]) + __ldg(&beta[lvl*16+o]);
        g_ppc[br][(nn*85+s)*16+o] = fmaxf(acc, 0.f);
    }
}

// ---------- K5: pyramid final convs via HMMA ----------
__global__ void __launch_bounds__(256) k_ppfinal_all(
        const float* __restrict__ ob0, const float* __restrict__ ob1, const float* __restrict__ ob2){
    __shared__ __nv_bfloat16 sB[128][72];
    __shared__ __nv_bfloat16 sO[64][72];
    __shared__ float spp[85*16];
    int bid = blockIdx.x;
    int br, n, t0;
    if (bid < 256){ br = 1; n = bid>>6; t0 = (bid&63)<<6; }
    else {
        int r = bid - 256;
        br = (r < 64) ? 0 : 2;
        int r2 = r & 63;
        n = r2 >> 4; t0 = (r2 & 15) << 6;
    }
    const float* ob = (br==0)?ob0:(br==1)?ob1:ob2;
    int hs = (br==1) ? 6 : 5;
    int H = 1 << hs;
    int P = H*H;
    const __nv_bfloat16* X = (br==0) ? g_g0 : (br==1) ? g_thin : g_phi0;
    const __nv_bfloat16* xin = X + (size_t)n*CC*P;
    int tid = threadIdx.x, w = tid>>5, lane = tid&31;
    for (int i=tid; i<512; i+=256){
        int c = i>>3, p8 = (i&7)*8;
        *(uint4*)&sB[c][p8] = *(const uint4*)&xin[c*P + t0 + p8];
    }
    for (int i=tid; i<1360; i+=256) spp[i] = g_ppc[br][n*1360 + i];
    __syncthreads();
    float invH = 1.0f / (float)H;
    for (int e = tid; e < 4096; e += 256){
        int u = e>>6, p = e&63;
        int lvl = u>>4, j = u&15;
        int pix = t0 + p; int y = pix >> hs, x = pix & (H-1);
        int ps = 8 >> lvl;
        int off = (lvl==0) ? 0 : (lvl==1 ? 64 : (lvl==2 ? 80 : 84));
        float sy = fminf(fmaxf((y+0.5f)*ps*invH - 0.5f, 0.f), (float)(ps-1));
        float sx = fminf(fmaxf((x+0.5f)*ps*invH - 0.5f, 0.f), (float)(ps-1));
        int yl=(int)sy; int yh=min(yl+1, ps-1); float fy=sy-yl;
        int xl=(int)sx; int xh=min(xl+1, ps-1); float fx=sx-xl;
        const float* b00 = spp + (off + yl*ps + xl)*16;
        const float* b01 = spp + (off + yl*ps + xh)*16;
        const float* b10 = spp + (off + yh*ps + xl)*16;
        const float* b11 = spp + (off + yh*ps + xh)*16;
        float v = (b00[j]*(1.f-fx)+b01[j]*fx)*(1.f-fy) + (b10[j]*(1.f-fx)+b11[j]*fx)*fy;
        sB[64+u][p] = __float2bfloat16(v);
    }
    __syncthreads();
    int mt = w & 3, ph = w >> 2;
    int ra = lane>>2, colb = (lane&3)*2, cq = (lane&3)*2;
    uint32_t aW[8][4];
    {
        const __nv_bfloat16* w0 = g_owcat + br*8192 + (mt*16 + ra)*128;
        const __nv_bfloat16* w8 = w0 + 8*128;
        #pragma unroll
        for (int kb=0;kb<8;kb++){
            int c0 = kb*16 + cq;
            aW[kb][0] = *(const uint32_t*)&w0[c0];
            aW[kb][1] = *(const uint32_t*)&w8[c0];
            aW[kb][2] = *(const uint32_t*)&w0[c0+8];
            aW[kb][3] = *(const uint32_t*)&w8[c0+8];
        }
    }
    int grow = (lane&7) + ((lane&8)?8:0);
    int gcol = (lane&16)?8:0;
    float acc[4][4];
    #pragma unroll
    for (int i=0;i<4;i++){ acc[i][0]=0.f;acc[i][1]=0.f;acc[i][2]=0.f;acc[i][3]=0.f; }
    #pragma unroll
    for (int kb=0;kb<8;kb++){
        int kr = kb*16 + grow;
        #pragma unroll
        for (int np=0;np<2;np++){
            uint32_t bg[4];
            ldsm4t(bg, s2u(&sB[kr][ph*32 + np*16 + gcol]));
            mma16816(acc[2*np], aW[kb], bg[0], bg[1]);
            mma16816(acc[2*np+1], aW[kb], bg[2], bg[3]);
        }
    }
    float ba = ob[mt*16 + ra], bb = ob[mt*16 + ra + 8];
    #pragma unroll
    for (int nf=0;nf<4;nf++){
        int px = ph*32 + (nf>>1)*16 + (nf&1)*8 + colb;
        sO[px][mt*16+ra]     = __float2bfloat16(acc[nf][0]+ba);
        sO[px+1][mt*16+ra]   = __float2bfloat16(acc[nf][1]+ba);
        sO[px][mt*16+ra+8]   = __float2bfloat16(acc[nf][2]+bb);
        sO[px+1][mt*16+ra+8] = __float2bfloat16(acc[nf][3]+bb);
    }
    __syncthreads();
    __nv_bfloat16* dst = (br==1) ? (g_th_h + ((size_t)n*4096 + t0)*64)
                      : (br==0) ? (g_gv_h + ((size_t)n*1024 + t0)*64)
                                : (g_phi_h + ((size_t)n*1024 + t0)*64);
    for (int i=tid; i<512; i+=256){
        int px = i>>3, o8 = (i&7)*8;
        *(uint4*)&dst[px*64 + o8] = *(const uint4*)&sO[px][o8];
    }
}

// ---------- bilinear on 256x256 ----------
__device__ __forceinline__ float bil256(const float* p, float sy, float sx){
    int yl=(int)sy; int yh=min(yl+1,255); float fy=sy-yl;
    int xl=(int)sx; int xh=min(xl+1,255); float fx=sx-xl;
    return (p[yl*256+xl]*(1.f-fx)+p[yl*256+xh]*fx)*(1.f-fy)
         + (p[yh*256+xl]*(1.f-fx)+p[yh*256+xh]*fx)*fy;
}

// ---------- K6: HMMA attention (256 thr, 64 q-rows, 2 CTA/SM) + fused z-conv ----------
__global__ void __launch_bounds__(256,2) k_attn_hmma(const float* __restrict__ depth,
                                                     const float* __restrict__ zb){
    __shared__ __align__(16) char RAW[36864];
    __shared__ float2 d2s[1024];
    __shared__ float d1s[64];
    __shared__ float ss3[2][64];
    __nv_bfloat16* sA = (__nv_bfloat16*)RAW;
    __nv_bfloat16* sB = (__nv_bfloat16*)(RAW + 18432);
    float* STF = (float*)RAW;
    int tid = threadIdx.x, w = tid>>5, lane = tid&31;
    int qt = w & 3, nh = w >> 2;
    int n = blockIdx.x>>6, q0 = (blockIdx.x&63)*64;

    const float* dm = depth + (size_t)n*65536;
    for (int i=tid;i<1024;i+=256){
        int yy=i>>5, xx=i&31;
        float d2 = bil256(dm, (float)(yy*255)/31.f, (float)(xx*255)/31.f);
        d2s[i] = make_float2(d2, __fdividef(1.f, d2+EPS6));
    }
    if (tid < 64){
        int q = q0 + tid;
        d1s[tid] = bil256(dm, (float)((q>>6)*255)/63.f, (float)((q&63)*255)/63.f);
    }
    const uint4* qg = (const uint4*)(g_th_h + ((size_t)(n*4096+q0))*64);
    for (int i=tid;i<512;i+=256)
        *(uint4*)&sA[(i>>3)*72 + (i&7)*8] = qg[i];
    __syncthreads();
    uint32_t sAu = s2u(sA), sBu = s2u(sB);
    uint32_t aQ[4][4];
    {
        int arow = qt*16 + (lane&15);
        int acol = (lane>>4)<<3;
        #pragma unroll
        for (int kb=0;kb<4;kb++)
            ldsm4(aQ[kb], sAu + (uint32_t)((arow*72 + kb*16 + acol)*2));
    }
    int ra = lane>>2, colb = (lane&3)*2;
    int r0_ = qt*16 + ra, r1_ = r0_ + 8;
    float d1a = d1s[r0_], d1b = d1s[r1_];
    float ir1a = __fdividef(1.f,d1a+EPS6), ir1b = __fdividef(1.f,d1b+EPS6);
    __syncthreads();

    int brow = (lane&7) + ((lane&16)?8:0);
    int bcol = (lane&8)?8:0;
    int grow = (lane&7) + ((lane&8)?8:0);
    int gcol = (lane&16)?8:0;
    const uint4* phg = (const uint4*)(g_phi_h + (size_t)n*65536);
    const uint4* gg  = (const uint4*)(g_gv_h + (size_t)n*65536);
    uint32_t* lg = g_lg + ((size_t)(n*4096 + q0))*512;
    int lrowa = r0_*512, lrowb = r1_*512;

    float s1a=0.f, s2a=0.f, s1b=0.f, s2b=0.f;

    for (int i=tid;i<1024;i+=256)
        *(uint4*)&sA[(i>>3)*72+(i&7)*8] = phg[i];
    __syncthreads();

    // ===== pass 1 =====
    for (int t=0;t<8;t++){
        uint32_t curu = (t&1) ? sBu : sAu;
        __nv_bfloat16* nxt = (t&1) ? sA : sB;
        uint4 pre[4];
        if (t<7){
            #pragma unroll
            for (int k=0;k<4;k++) pre[k] = phg[(t+1)*1024 + tid + k*256];
        }
        float L[8][4];
        #pragma unroll
        for (int nt=0;nt<8;nt++){ L[nt][0]=0.f;L[nt][1]=0.f;L[nt][2]=0.f;L[nt][3]=0.f; }
        #pragma unroll
        for (int kb=0;kb<4;kb++){
            #pragma unroll
            for (int ng=0;ng<4;ng++){
                uint32_t bq[4];
                int br_ = nh*64 + ng*16 + brow;
                ldsm4(bq, curu + (uint32_t)((br_*72 + kb*16 + bcol)*2));
                mma16816(L[2*ng], aQ[kb], bq[0], bq[1]);
                mma16816(L[2*ng+1], aQ[kb], bq[2], bq[3]);
            }
        }
        if (t<7){
            #pragma unroll
            for (int k=0;k<4;k++){
                int i0 = tid + k*256;
                *(uint4*)&nxt[(i0>>3)*72+(i0&7)*8] = pre[k];
            }
        }
        int cwb = t*64 + nh*32 + (lane&3);
        #pragma unroll
        for (int nt=0;nt<8;nt++){
            int v = t*128 + nh*64 + nt*8 + colb;
            float2 dp = d2s[v], dq = d2s[v+1];
            float r0 = fminf(d1a*dp.y, dp.x*ir1a);
            float r1 = fminf(d1a*dq.y, dq.x*ir1a);
            float r2 = fminf(d1b*dp.y, dp.x*ir1b);
            float r3 = fminf(d1b*dq.y, dq.x*ir1b);
            float p0 = __expf(r0-1.f), p1 = __expf(r1-1.f);
            float p2 = __expf(r2-1.f), p3 = __expf(r3-1.f);
            s2a += p0+p1; s2b += p2+p3;
            float el0 = __expf(L[nt][0]), el1 = __expf(L[nt][1]);
            float el2 = __expf(L[nt][2]), el3 = __expf(L[nt][3]);
            s1a += el0+el1; s1b += el2+el3;
            __half2 ha = __floats2half2_rn(el0*p0*E1F, el1*p1*E1F);
            __half2 hb = __floats2half2_rn(el2*p2*E1F, el3*p3*E1F);
            lg[lrowa + cwb + nt*4] = *(uint32_t*)&ha;
            lg[lrowb + cwb + nt*4] = *(uint32_t*)&hb;
        }
        __syncthreads();
    }

    #pragma unroll
    for (int o=1;o<=2;o<<=1){
        s1a += __shfl_xor_sync(~0u,s1a,o);
        s1b += __shfl_xor_sync(~0u,s1b,o);
        s2a += __shfl_xor_sync(~0u,s2a,o);
        s2b += __shfl_xor_sync(~0u,s2b,o);
    }
    if ((lane&3)==0){
        STF[      nh*64 + r0_] = s1a;  STF[      nh*64 + r1_] = s1b;
        STF[128 + nh*64 + r0_] = s2a;  STF[128 + nh*64 + r1_] = s2b;
    }
    __syncthreads();
    float S1a = STF[r0_] + STF[64+r0_];
    float S2a = (STF[128+r0_] + STF[192+r0_]) * E1F;
    float S1b = STF[r1_] + STF[64+r1_];
    float S2b = (STF[128+r1_] + STF[192+r1_]) * E1F;
    float c1a = __fdividef(1.f, S1a*S2a);
    float c1b = __fdividef(1.f, S1b*S2b);
    __syncthreads();

    // ===== pass 2 =====
    float Y[8][4];
    #pragma unroll
    for (int i=0;i<8;i++){ Y[i][0]=0.f;Y[i][1]=0.f;Y[i][2]=0.f;Y[i][3]=0.f; }
    float s3a=0.f, s3b=0.f;
    for (int i=tid;i<1024;i+=256)
        *(uint4*)&sA[(i>>3)*72+(i&7)*8] = gg[i];
    __syncthreads();
    for (int t=0;t<8;t++){
        uint32_t curu = (t&1) ? sBu : sAu;
        __nv_bfloat16* nxt = (t&1) ? sA : sB;
        uint4 pre[4];
        if (t<7){
            #pragma unroll
            for (int k=0;k<4;k++) pre[k] = gg[(t+1)*1024 + tid + k*256];
        }
        int cwb = t*64 + nh*32 + (lane&3);
        uint32_t lwa[8], lwb[8];
        #pragma unroll
        for (int nt=0;nt<8;nt++){
            lwa[nt] = lg[lrowa + cwb + nt*4];
            lwb[nt] = lg[lrowb + cwb + nt*4];
        }
        uint32_t ek[4][4];
        #pragma unroll
        for (int nt=0;nt<8;nt++){
            float2 la = __half22float2(*(__half2*)&lwa[nt]);
            float2 lb = __half22float2(*(__half2*)&lwb[nt]);
            float e0 = expp(c1a*la.x);
            float e1 = expp(c1a*la.y);
            float e2 = expp(c1b*lb.x);
            float e3 = expp(c1b*lb.y);
            s3a += e0+e1; s3b += e2+e3;
            __nv_bfloat162 pa2 = __floats2bfloat162_rn(e0,e1);
            __nv_bfloat162 pb2 = __floats2bfloat162_rn(e2,e3);
            int kb = nt>>1, hh = (nt&1)<<1;
            ek[kb][hh]   = *(uint32_t*)&pa2;
            ek[kb][hh+1] = *(uint32_t*)&pb2;
        }
        #pragma unroll
        for (int kb=0;kb<4;kb++){
            #pragma unroll
            for (int np=0;np<4;np++){
                uint32_t bg[4];
                int gr = nh*64 + kb*16 + grow;
                ldsm4t(bg, curu + (uint32_t)((gr*72 + np*16 + gcol)*2));
                mma16816(Y[2*np], ek[kb], bg[0], bg[1]);
                mma16816(Y[2*np+1], ek[kb], bg[2], bg[3]);
            }
        }
        if (t<7){
            #pragma unroll
            for (int k=0;k<4;k++){
                int i0 = tid + k*256;
                *(uint4*)&nxt[(i0>>3)*72+(i0&7)*8] = pre[k];
            }
        }
        __syncthreads();
    }
    s3a += __shfl_xor_sync(~0u,s3a,1); s3a += __shfl_xor_sync(~0u,s3a,2);
    s3b += __shfl_xor_sync(~0u,s3b,1); s3b += __shfl_xor_sync(~0u,s3b,2);
    if ((lane&3)==0){ ss3[nh][r0_] = s3a; ss3[nh][r1_] = s3b; }
    __nv_bfloat16 (*ysh)[68] = (__nv_bfloat16(*)[68])RAW;
    __nv_bfloat16 (*sYf)[72] = (__nv_bfloat16(*)[72])(RAW + 18432);
    __syncthreads();
    if (nh == 0){
        #pragma unroll
        for (int np2=0;np2<8;np2++){
            int c_ = np2*8 + colb;
            ysh[r0_][c_]   = __float2bfloat16(Y[np2][0]);
            ysh[r0_][c_+1] = __float2bfloat16(Y[np2][1]);
            ysh[r1_][c_]   = __float2bfloat16(Y[np2][2]);
            ysh[r1_][c_+1] = __float2bfloat16(Y[np2][3]);
        }
    }
    __syncthreads();
    if (nh == 1){
        float i3a = __fdividef(1.f, ss3[0][r0_] + ss3[1][r0_]);
        float i3b = __fdividef(1.f, ss3[0][r1_] + ss3[1][r1_]);
        #pragma unroll
        for (int np2=0;np2<8;np2++){
            int c_ = np2*8 + colb;
            __nv_bfloat162 va = __floats2bfloat162_rn(
                (Y[np2][0]+__bfloat162float(ysh[r0_][c_]))*i3a,
                (Y[np2][1]+__bfloat162float(ysh[r0_][c_+1]))*i3a);
            __nv_bfloat162 vb = __floats2bfloat162_rn(
                (Y[np2][2]+__bfloat162float(ysh[r1_][c_]))*i3b,
                (Y[np2][3]+__bfloat162float(ysh[r1_][c_+1]))*i3b);
            *(uint32_t*)&sYf[r0_][c_] = *(uint32_t*)&va;
            *(uint32_t*)&sYf[r1_][c_] = *(uint32_t*)&vb;
        }
    }
    __syncthreads();
    // fused z conv: 8 warps = 8 out-tiles of 16 ch, each over 64 px
    {
        uint32_t aWz[4][4];
        const __nv_bfloat16* w0 = g_zw_h + (w*16 + ra)*64;
        const __nv_bfloat16* w8 = w0 + 8*64;
        #pragma unroll
        for (int kb=0;kb<4;kb++){
            int c0 = kb*16 + colb;
            aWz[kb][0] = *(const uint32_t*)&w0[c0];
            aWz[kb][1] = *(const uint32_t*)&w8[c0];
            aWz[kb][2] = *(const uint32_t*)&w0[c0+8];
            aWz[kb][3] = *(const uint32_t*)&w8[c0+8];
        }
        float accz[8][4];
        #pragma unroll
        for (int i=0;i<8;i++){ accz[i][0]=0.f;accz[i][1]=0.f;accz[i][2]=0.f;accz[i][3]=0.f; }
        #pragma unroll
        for (int kb=0;kb<4;kb++){
            #pragma unroll
            for (int ng=0;ng<4;ng++){
                uint32_t bq[4];
                ldsm4(bq, s2u(&sYf[ng*16 + brow][kb*16 + bcol]));
                mma16816(accz[2*ng], aWz[kb], bq[0], bq[1]);
                mma16816(accz[2*ng+1], aWz[kb], bq[2], bq[3]);
            }
        }
        float ba = zb[w*16 + ra], bb = zb[w*16 + ra + 8];
        float* zr0 = g_z + ((size_t)n*C + w*16 + ra)*4096 + q0;
        float* zr8 = zr0 + 8*4096;
        #pragma unroll
        for (int ng=0;ng<4;ng++){
            #pragma unroll
            for (int j=0;j<2;j++){
                int px = ng*16 + j*8 + colb;
                *(float2*)&zr0[px] = make_float2(accz[2*ng+j][0]+ba, accz[2*ng+j][1]+ba);
                *(float2*)&zr8[px] = make_float2(accz[2*ng+j][2]+bb, accz[2*ng+j][3]+bb);
            }
        }
    }
}

// ---------- K7: epilogue ----------
__global__ void k_epi(const float* __restrict__ x, float* __restrict__ out){
    int idx = blockIdx.x*blockDim.x + threadIdx.x;
    if (idx >= NB*C*H0*H0/4) return;
    int xb4 = (idx & 63) << 2;
    int Y = (idx>>6) & 255;
    int nch = idx >> 14;
    float sy = (float)(Y*63)/255.f;
    int yl=(int)sy; int yh=min(yl+1,63); float fy=sy-yl;
    const float* z0 = g_z + (size_t)nch*4096 + yl*64;
    const float* z1 = g_z + (size_t)nch*4096 + yh*64;
    float4 r;
    float* rp = &r.x;
    #pragma unroll
    for (int k=0;k<4;k++){
        int X_ = xb4 + k;
        float sx = (float)(X_*63)/255.f;
        int xl=(int)sx; int xh=min(xl+1,63); float fx=sx-xl;
        rp[k] = (z0[xl]*(1.f-fx)+z0[xh]*fx)*(1.f-fy)
              + (z1[xl]*(1.f-fx)+z1[xh]*fx)*fy;
    }
    float4 xin = *(const float4*)(x + ((size_t)idx<<2));
    r.x += xin.x; r.y += xin.y; r.z += xin.z; r.w += xin.w;
    *(float4*)(out + ((size_t)idx<<2)) = r;
}

// ---------- host ----------
extern "C" void kernel_launch(void* const* d_in, const int* in_sizes, int n_in,
                              void* d_out, int out_size){
    const float* x       = (const float*)d_in[0];
    const float* depth   = (const float*)d_in[1];
    const float* down_w  = (const float*)d_in[2];
    const float* theta_w = (const float*)d_in[3];
    const float* theta_b = (const float*)d_in[4];
    const float* phi_w   = (const float*)d_in[5];
    const float* phi_b   = (const float*)d_in[6];
    const float* g_w     = (const float*)d_in[7];
    const float* g_b     = (const float*)d_in[8];
    const float* z_w     = (const float*)d_in[9];
    const float* z_b     = (const float*)d_in[10];
    const float* ppg_pw  = (const float*)d_in[11];
    const float* ppg_gam = (const float*)d_in[12];
    const float* ppg_bet = (const float*)d_in[13];
    const float* ppg_ow  = (const float*)d_in[14];
    const float* ppg_ob  = (const float*)d_in[15];
    const float* ppt_pw  = (const float*)d_in[16];
    const float* ppt_gam = (const float*)d_in[17];
    const float* ppt_bet = (const float*)d_in[18];
    const float* ppt_ow  = (const float*)d_in[19];
    const float* ppt_ob  = (const float*)d_in[20];
    const float* ppp_pw  = (const float*)d_in[21];
    const float* ppp_gam = (const float*)d_in[22];
    const float* ppp_bet = (const float*)d_in[23];
    const float* ppp_ow  = (const float*)d_in[24];
    const float* ppp_ob  = (const float*)d_in[25];
    float* out = (float*)d_out;

    k_down<<<(NB*C*HD*HD + 7*8192)/256, 256>>>(x, down_w, theta_w, g_w, phi_w, z_w,
                                               ppg_ow, ppt_ow, ppp_ow);
    k_convs_hmma<<<NB*32, 384>>>(theta_b, g_b, phi_b);
    k_pool_all<<<3*NB*64, 256>>>();
    k_levelconv_all<<<(3*NB*85*16*8 + 255)/256, 256>>>(ppg_pw, ppg_gam, ppg_bet,
                                                       ppt_pw, ppt_gam, ppt_bet,
                                                       ppp_pw, ppp_gam, ppp_bet);
    k_ppfinal_all<<<384, 256>>>(ppg_ob, ppt_ob, ppp_ob);
    k_attn_hmma<<<NB*64, 256>>>(depth, z_b);
    k_epi<<<(NB*C*H0*H0/4 + 255)/256, 256>>>(x, out);
}